// round 1
// baseline (speedup 1.0000x reference)
#include <cuda_runtime.h>
#include <math.h>

#define DIMC   1024
#define NHEAD  16
#define DHEAD  64
#define SEQ    2048
#define NB     2
#define NROWS  (NB * SEQ)       // 4096
#define ATT_SCALE 0.125f        // 64^-0.5

#define QS_STRIDE 65
#define VS_STRIDE 68

// Scratch (device globals; no allocation allowed)
__device__ float g_xn[(size_t)NROWS * DIMC];
__device__ float g_cn[(size_t)NROWS * DIMC];
__device__ float g_q [(size_t)NROWS * DIMC];
__device__ float g_k [(size_t)NROWS * DIMC];
__device__ float g_v [(size_t)NROWS * DIMC];
__device__ float g_ao[(size_t)NROWS * DIMC];

// ---------------------------------------------------------------------------
// LayerNorm: one block per row of 1024 floats, 256 threads, float4 per thread
// ---------------------------------------------------------------------------
__global__ void __launch_bounds__(256) ln_kernel(const float* __restrict__ in,
                                                 const float* __restrict__ w,
                                                 const float* __restrict__ bvec,
                                                 float* __restrict__ out) {
    int row = blockIdx.x;
    int t = threadIdx.x;
    const float4* rp = (const float4*)(in + (size_t)row * DIMC);
    float4 v = rp[t];
    float s  = v.x + v.y + v.z + v.w;
    float ss = v.x*v.x + v.y*v.y + v.z*v.z + v.w*v.w;

    __shared__ float s_sum[8], s_sq[8], s_stats[2];
    #pragma unroll
    for (int o = 16; o; o >>= 1) {
        s  += __shfl_xor_sync(0xffffffffu, s,  o);
        ss += __shfl_xor_sync(0xffffffffu, ss, o);
    }
    int lane = t & 31, wid = t >> 5;
    if (lane == 0) { s_sum[wid] = s; s_sq[wid] = ss; }
    __syncthreads();
    if (t == 0) {
        float a = 0.f, b2 = 0.f;
        #pragma unroll
        for (int i = 0; i < 8; i++) { a += s_sum[i]; b2 += s_sq[i]; }
        float mean = a * (1.0f / DIMC);
        float var  = b2 * (1.0f / DIMC) - mean * mean;
        s_stats[0] = mean;
        s_stats[1] = rsqrtf(var + 1e-5f);
    }
    __syncthreads();
    float mean = s_stats[0], inv = s_stats[1];
    float4 wv = ((const float4*)w)[t];
    float4 bv = ((const float4*)bvec)[t];
    float4 o;
    o.x = (v.x - mean) * inv * wv.x + bv.x;
    o.y = (v.y - mean) * inv * wv.y + bv.y;
    o.z = (v.z - mean) * inv * wv.z + bv.z;
    o.w = (v.w - mean) * inv * wv.w + bv.w;
    ((float4*)(out + (size_t)row * DIMC))[t] = o;
}

// ---------------------------------------------------------------------------
// SGEMM:  C[M][N] = A[M][K] * B[N][K]^T  (+ bias[N])
// 128x128 tile, BK=8, 256 threads, 8x8 microtile per thread.
// ---------------------------------------------------------------------------
template<bool BIAS>
__global__ void __launch_bounds__(256) gemm_nt(const float* __restrict__ A,
                                               const float* __restrict__ Bw,
                                               const float* __restrict__ bias,
                                               float* __restrict__ C,
                                               int M, int N, int K) {
    __shared__ float As[8][132];
    __shared__ float Bs[8][132];
    int tid = threadIdx.x;
    int mBase = blockIdx.y * 128;
    int nBase = blockIdx.x * 128;
    int tm = tid >> 4, tn = tid & 15;

    float acc[8][8];
    #pragma unroll
    for (int i = 0; i < 8; i++)
        #pragma unroll
        for (int j = 0; j < 8; j++) acc[i][j] = 0.f;

    int lrow = tid >> 1;
    int lk   = (tid & 1) * 4;
    const float* Ap = A  + (size_t)(mBase + lrow) * K + lk;
    const float* Bp = Bw + (size_t)(nBase + lrow) * K + lk;

    for (int k0 = 0; k0 < K; k0 += 8) {
        float4 av = *(const float4*)(Ap + k0);
        float4 bv = *(const float4*)(Bp + k0);
        __syncthreads();
        As[lk+0][lrow] = av.x; As[lk+1][lrow] = av.y;
        As[lk+2][lrow] = av.z; As[lk+3][lrow] = av.w;
        Bs[lk+0][lrow] = bv.x; Bs[lk+1][lrow] = bv.y;
        Bs[lk+2][lrow] = bv.z; Bs[lk+3][lrow] = bv.w;
        __syncthreads();
        #pragma unroll
        for (int kk = 0; kk < 8; kk++) {
            float a[8], b[8];
            *(float4*)(a)     = *(const float4*)&As[kk][tm * 8];
            *(float4*)(a + 4) = *(const float4*)&As[kk][tm * 8 + 4];
            *(float4*)(b)     = *(const float4*)&Bs[kk][tn * 8];
            *(float4*)(b + 4) = *(const float4*)&Bs[kk][tn * 8 + 4];
            #pragma unroll
            for (int i = 0; i < 8; i++)
                #pragma unroll
                for (int j = 0; j < 8; j++)
                    acc[i][j] = fmaf(a[i], b[j], acc[i][j]);
        }
    }

    #pragma unroll
    for (int i = 0; i < 8; i++) {
        size_t row = (size_t)(mBase + tm * 8 + i);
        float* cp = C + row * N + nBase + tn * 8;
        #pragma unroll
        for (int j4 = 0; j4 < 8; j4 += 4) {
            float4 o;
            o.x = acc[i][j4+0]; o.y = acc[i][j4+1];
            o.z = acc[i][j4+2]; o.w = acc[i][j4+3];
            if (BIAS) {
                const float* bp = bias + nBase + tn * 8 + j4;
                o.x += bp[0]; o.y += bp[1]; o.z += bp[2]; o.w += bp[3];
            }
            *(float4*)(cp + j4) = o;
        }
    }
}

// ---------------------------------------------------------------------------
// Flash attention (fp32): grid (n/64, b*h); 256 threads as 16x16;
// each thread owns a 4x4 score subtile and 4x4 of the 64-wide output.
// q/k/v kept in natural [b, seq, 1024] layout; head = column slice.
// ---------------------------------------------------------------------------
__global__ void __launch_bounds__(256) attn_kernel(const float* __restrict__ q,
                                                   const float* __restrict__ k,
                                                   const float* __restrict__ v,
                                                   const float* __restrict__ alibi,
                                                   float* __restrict__ out) {
    extern __shared__ float smx[];
    float* Qs = smx;                           // 64 * 65
    float* Ks = Qs + 64 * QS_STRIDE;           // 64 * 65
    float* Vs = Ks + 64 * QS_STRIDE;           // 64 * 68
    float* Ps = Vs + 64 * VS_STRIDE;           // 64 * 68

    int bh = blockIdx.y;
    int bi = bh >> 4;
    int h  = bh & 15;
    int i0 = blockIdx.x * 64;
    int tid = threadIdx.x;
    int ty = tid >> 4, tx = tid & 15;

    // Load Q tile (64 rows x 64 d), coalesced float4, scalar-store transpose-free
    const float* qb = q + ((size_t)bi * SEQ + i0) * DIMC + h * DHEAD;
    #pragma unroll
    for (int u = 0; u < 4; u++) {
        int f = tid + 256 * u;         // float4 index within tile
        int r = f >> 4;
        int c = (f & 15) << 2;
        float4 val = *(const float4*)(qb + (size_t)r * DIMC + c);
        Qs[r * QS_STRIDE + c + 0] = val.x;
        Qs[r * QS_STRIDE + c + 1] = val.y;
        Qs[r * QS_STRIDE + c + 2] = val.z;
        Qs[r * QS_STRIDE + c + 3] = val.w;
    }

    float m_i[4], l_i[4], acc[4][4];
    #pragma unroll
    for (int i = 0; i < 4; i++) {
        m_i[i] = -INFINITY; l_i[i] = 0.f;
        #pragma unroll
        for (int j = 0; j < 4; j++) acc[i][j] = 0.f;
    }

    const float* kb = k + (size_t)bi * SEQ * DIMC + h * DHEAD;
    const float* vb = v + (size_t)bi * SEQ * DIMC + h * DHEAD;

    for (int j0 = 0; j0 < SEQ; j0 += 64) {
        __syncthreads();   // prior-iteration Ks/Vs/Ps reads done (also orders Qs on iter 0)
        #pragma unroll
        for (int u = 0; u < 4; u++) {
            int f = tid + 256 * u;
            int r = f >> 4;
            int c = (f & 15) << 2;
            float4 kv4 = *(const float4*)(kb + (size_t)(j0 + r) * DIMC + c);
            Ks[r * QS_STRIDE + c + 0] = kv4.x;
            Ks[r * QS_STRIDE + c + 1] = kv4.y;
            Ks[r * QS_STRIDE + c + 2] = kv4.z;
            Ks[r * QS_STRIDE + c + 3] = kv4.w;
            float4 vv4 = *(const float4*)(vb + (size_t)(j0 + r) * DIMC + c);
            *(float4*)&Vs[r * VS_STRIDE + c] = vv4;
        }
        __syncthreads();

        // S = Q K^T
        float s[4][4];
        #pragma unroll
        for (int i = 0; i < 4; i++)
            #pragma unroll
            for (int j = 0; j < 4; j++) s[i][j] = 0.f;
        #pragma unroll 8
        for (int kk = 0; kk < 64; kk++) {
            float qv[4], kv[4];
            #pragma unroll
            for (int i = 0; i < 4; i++) qv[i] = Qs[(ty * 4 + i) * QS_STRIDE + kk];
            #pragma unroll
            for (int j = 0; j < 4; j++) kv[j] = Ks[(tx * 4 + j) * QS_STRIDE + kk];
            #pragma unroll
            for (int i = 0; i < 4; i++)
                #pragma unroll
                for (int j = 0; j < 4; j++)
                    s[i][j] = fmaf(qv[i], kv[j], s[i][j]);
        }

        // scale + alibi
        const float* ab = alibi + ((size_t)h * SEQ + i0 + ty * 4) * SEQ + j0 + tx * 4;
        #pragma unroll
        for (int i = 0; i < 4; i++) {
            float4 al = *(const float4*)(ab + (size_t)i * SEQ);
            s[i][0] = s[i][0] * ATT_SCALE + al.x;
            s[i][1] = s[i][1] * ATT_SCALE + al.y;
            s[i][2] = s[i][2] * ATT_SCALE + al.z;
            s[i][3] = s[i][3] * ATT_SCALE + al.w;
        }

        // online softmax update (row = 16 tx lanes x 4 cols; xor-shfl over 16-lane halves)
        #pragma unroll
        for (int i = 0; i < 4; i++) {
            float rm = fmaxf(fmaxf(s[i][0], s[i][1]), fmaxf(s[i][2], s[i][3]));
            #pragma unroll
            for (int o = 8; o; o >>= 1)
                rm = fmaxf(rm, __shfl_xor_sync(0xffffffffu, rm, o));
            float mn = fmaxf(m_i[i], rm);
            float alpha = expf(m_i[i] - mn);
            m_i[i] = mn;
            float rs = 0.f;
            #pragma unroll
            for (int j = 0; j < 4; j++) { s[i][j] = expf(s[i][j] - mn); rs += s[i][j]; }
            #pragma unroll
            for (int o = 8; o; o >>= 1)
                rs += __shfl_xor_sync(0xffffffffu, rs, o);
            l_i[i] = l_i[i] * alpha + rs;
            #pragma unroll
            for (int j = 0; j < 4; j++) acc[i][j] *= alpha;
            *(float4*)&Ps[(ty * 4 + i) * VS_STRIDE + tx * 4] =
                make_float4(s[i][0], s[i][1], s[i][2], s[i][3]);
        }
        __syncthreads();

        // O += P V
        #pragma unroll 8
        for (int j = 0; j < 64; j++) {
            float4 vv = *(const float4*)&Vs[j * VS_STRIDE + tx * 4];
            #pragma unroll
            for (int i = 0; i < 4; i++) {
                float pj = Ps[(ty * 4 + i) * VS_STRIDE + j];
                acc[i][0] = fmaf(pj, vv.x, acc[i][0]);
                acc[i][1] = fmaf(pj, vv.y, acc[i][1]);
                acc[i][2] = fmaf(pj, vv.z, acc[i][2]);
                acc[i][3] = fmaf(pj, vv.w, acc[i][3]);
            }
        }
    }

    // normalize and write to [b, n, h*64 + d]
    #pragma unroll
    for (int i = 0; i < 4; i++) {
        float invl = 1.0f / l_i[i];
        size_t row = (size_t)bi * SEQ + i0 + ty * 4 + i;
        float4 o = make_float4(acc[i][0] * invl, acc[i][1] * invl,
                               acc[i][2] * invl, acc[i][3] * invl);
        *(float4*)(out + row * DIMC + h * DHEAD + tx * 4) = o;
    }
}

// ---------------------------------------------------------------------------
extern "C" void kernel_launch(void* const* d_in, const int* in_sizes, int n_in,
                              void* d_out, int out_size) {
    const float* x     = (const float*)d_in[0];
    const float* ctx   = (const float*)d_in[1];
    const float* alibi = (const float*)d_in[2];
    const float* Wq    = (const float*)d_in[3];
    const float* Wk    = (const float*)d_in[4];
    const float* Wv    = (const float*)d_in[5];
    const float* Wo    = (const float*)d_in[6];
    const float* bo    = (const float*)d_in[7];
    const float* ln_w  = (const float*)d_in[8];
    const float* ln_b  = (const float*)d_in[9];
    float* out = (float*)d_out;

    float *xn, *cn, *q, *k, *v, *ao;
    cudaGetSymbolAddress((void**)&xn, g_xn);
    cudaGetSymbolAddress((void**)&cn, g_cn);
    cudaGetSymbolAddress((void**)&q,  g_q);
    cudaGetSymbolAddress((void**)&k,  g_k);
    cudaGetSymbolAddress((void**)&v,  g_v);
    cudaGetSymbolAddress((void**)&ao, g_ao);

    ln_kernel<<<NROWS, 256>>>(x,   ln_w, ln_b, xn);
    ln_kernel<<<NROWS, 256>>>(ctx, ln_w, ln_b, cn);

    dim3 gg(DIMC / 128, NROWS / 128);
    gemm_nt<false><<<gg, 256>>>(xn, Wq, nullptr, q, NROWS, DIMC, DIMC);
    gemm_nt<false><<<gg, 256>>>(cn, Wk, nullptr, k, NROWS, DIMC, DIMC);
    gemm_nt<false><<<gg, 256>>>(cn, Wv, nullptr, v, NROWS, DIMC, DIMC);

    size_t smem = (size_t)(2 * 64 * QS_STRIDE + 2 * 64 * VS_STRIDE) * sizeof(float);
    cudaFuncSetAttribute(attn_kernel, cudaFuncAttributeMaxDynamicSharedMemorySize, (int)smem);
    dim3 ga(SEQ / 64, NB * NHEAD);
    attn_kernel<<<ga, 256, smem>>>(q, k, v, alibi, ao);

    gemm_nt<true><<<gg, 256>>>(ao, Wo, bo, out, NROWS, DIMC, DIMC);
}

// round 6
// speedup vs baseline: 1.3719x; 1.3719x over previous
#include <cuda_runtime.h>
#include <cuda_fp16.h>
#include <math.h>
#include <stdint.h>

#define DIMC   1024
#define NHEAD  16
#define DHEAD  64
#define SEQ    2048
#define NB     2
#define NROWS  (NB * SEQ)       // 4096
#define ATT_SCALE 0.125f

#define QS_STRIDE 65
#define VS_STRIDE 68

// ---------------------------------------------------------------------------
// Scratch (device globals; no allocation allowed)
// ---------------------------------------------------------------------------
__device__ __half g_xhi[(size_t)NROWS * DIMC];
__device__ __half g_xlo[(size_t)NROWS * DIMC];
__device__ __half g_chi[(size_t)NROWS * DIMC];
__device__ __half g_clo[(size_t)NROWS * DIMC];
__device__ __half g_ahi[(size_t)NROWS * DIMC];
__device__ __half g_alo[(size_t)NROWS * DIMC];
__device__ __half g_wb[8ul * DIMC * DIMC];   // 4 weights x (hi,lo)
__device__ float g_q [(size_t)NROWS * DIMC];
__device__ float g_k [(size_t)NROWS * DIMC];
__device__ float g_v [(size_t)NROWS * DIMC];

// ---------------------------------------------------------------------------
// PTX helpers (all sm_80-baseline; no sm_103a-only features)
// ---------------------------------------------------------------------------
__device__ __forceinline__ uint32_t smem_u32(const void* p) {
    uint32_t a;
    asm("{ .reg .u64 t; cvta.to.shared.u64 t, %1; cvt.u32.u64 %0, t; }" : "=r"(a) : "l"(p));
    return a;
}
__device__ __forceinline__ void cp16(uint32_t dst, const void* src) {
    asm volatile("cp.async.cg.shared.global [%0], [%1], 16;" :: "r"(dst), "l"(src));
}
__device__ __forceinline__ void ldsm4(uint32_t* r, uint32_t addr) {
    asm volatile("ldmatrix.sync.aligned.m8n8.x4.shared.b16 {%0,%1,%2,%3}, [%4];"
        : "=r"(r[0]), "=r"(r[1]), "=r"(r[2]), "=r"(r[3]) : "r"(addr));
}
__device__ __forceinline__ void mma16816(float* c, const uint32_t* a,
                                         uint32_t b0, uint32_t b1) {
    asm volatile("mma.sync.aligned.m16n8k16.row.col.f32.f16.f16.f32 "
        "{%0,%1,%2,%3}, {%4,%5,%6,%7}, {%8,%9}, {%0,%1,%2,%3};"
        : "+f"(c[0]), "+f"(c[1]), "+f"(c[2]), "+f"(c[3])
        : "r"(a[0]), "r"(a[1]), "r"(a[2]), "r"(a[3]), "r"(b0), "r"(b1));
}

// ---------------------------------------------------------------------------
// LayerNorm -> fp16 hi/lo split outputs
// ---------------------------------------------------------------------------
__global__ void __launch_bounds__(256) ln_kernel(const float* __restrict__ in,
                                                 const float* __restrict__ w,
                                                 const float* __restrict__ bvec,
                                                 __half* __restrict__ hi,
                                                 __half* __restrict__ lo) {
    int row = blockIdx.x;
    int t = threadIdx.x;
    const float4* rp = (const float4*)(in + (size_t)row * DIMC);
    float4 v = rp[t];
    float s  = v.x + v.y + v.z + v.w;
    float ss = v.x*v.x + v.y*v.y + v.z*v.z + v.w*v.w;

    __shared__ float s_sum[8], s_sq[8], s_stats[2];
    #pragma unroll
    for (int o = 16; o; o >>= 1) {
        s  += __shfl_xor_sync(0xffffffffu, s,  o);
        ss += __shfl_xor_sync(0xffffffffu, ss, o);
    }
    int lane = t & 31, wid = t >> 5;
    if (lane == 0) { s_sum[wid] = s; s_sq[wid] = ss; }
    __syncthreads();
    if (t == 0) {
        float a = 0.f, b2 = 0.f;
        #pragma unroll
        for (int i = 0; i < 8; i++) { a += s_sum[i]; b2 += s_sq[i]; }
        float mean = a * (1.0f / DIMC);
        float var  = b2 * (1.0f / DIMC) - mean * mean;
        s_stats[0] = mean;
        s_stats[1] = rsqrtf(var + 1e-5f);
    }
    __syncthreads();
    float mean = s_stats[0], inv = s_stats[1];
    float4 wv = ((const float4*)w)[t];
    float4 bv = ((const float4*)bvec)[t];
    float y[4];
    y[0] = (v.x - mean) * inv * wv.x + bv.x;
    y[1] = (v.y - mean) * inv * wv.y + bv.y;
    y[2] = (v.z - mean) * inv * wv.z + bv.z;
    y[3] = (v.w - mean) * inv * wv.w + bv.w;

    __half h[4], l[4];
    #pragma unroll
    for (int i = 0; i < 4; i++) {
        h[i] = __float2half_rn(y[i]);
        l[i] = __float2half_rn(y[i] - __half2float(h[i]));
    }
    size_t base = (size_t)row * DIMC + t * 4;
    *(__half2*)(hi + base)     = __halves2half2(h[0], h[1]);
    *(__half2*)(hi + base + 2) = __halves2half2(h[2], h[3]);
    *(__half2*)(lo + base)     = __halves2half2(l[0], l[1]);
    *(__half2*)(lo + base + 2) = __halves2half2(l[2], l[3]);
}

// Split a float matrix into fp16 hi/lo
__global__ void __launch_bounds__(256) split_kernel(const float4* __restrict__ in,
                                                    __half* __restrict__ hi,
                                                    __half* __restrict__ lo, int n4) {
    int i = blockIdx.x * blockDim.x + threadIdx.x;
    if (i >= n4) return;
    float4 v = in[i];
    float y[4] = {v.x, v.y, v.z, v.w};
    __half h[4], l[4];
    #pragma unroll
    for (int j = 0; j < 4; j++) {
        h[j] = __float2half_rn(y[j]);
        l[j] = __float2half_rn(y[j] - __half2float(h[j]));
    }
    size_t base = (size_t)i * 4;
    *(__half2*)(hi + base)     = __halves2half2(h[0], h[1]);
    *(__half2*)(hi + base + 2) = __halves2half2(h[2], h[3]);
    *(__half2*)(lo + base)     = __halves2half2(l[0], l[1]);
    *(__half2*)(lo + base + 2) = __halves2half2(l[2], l[3]);
}

// ---------------------------------------------------------------------------
// mma.sync fp16-split GEMM: C[M][N] = A[M][K] B[N][K]^T (+bias), fp32 out.
// 128x128 CTA tile, BK=32, 2-stage cp.async double buffer, 8 warps (64x32
// warp tiles, 2m x 4n). 3 passes/k-step: hi*hi + hi*lo + lo*hi.
// smem rows padded to 80B (40 fp16) -> conflict-free LDSM, no swizzle.
// ---------------------------------------------------------------------------
#define BK        32
#define NCHUNK    (DIMC / BK)            // 32
#define ROWB      80                     // bytes per smem row (32 fp16 + pad)
#define MATB      (128 * ROWB)           // 10240 bytes per matrix tile
#define STAGE     (4 * MATB)             // Ahi, Alo, Bhi, Blo
#define GSMEM     (2 * STAGE)            // 81920

template<bool BIAS>
__global__ void __launch_bounds__(256, 2) gemm_mma(
    const __half* __restrict__ Ahi, const __half* __restrict__ Alo,
    const __half* __restrict__ Bhi, const __half* __restrict__ Blo,
    const float* __restrict__ bias, float* __restrict__ C)
{
    extern __shared__ char smem[];
    uint32_t sb = smem_u32(smem);

    int tid = threadIdx.x, wid = tid >> 5, lane = tid & 31;
    int mBase = blockIdx.y * 128, nBase = blockIdx.x * 128;

    // loader geometry: 512 16B-chunks per matrix tile / 256 threads
    int lrow = tid & 127;            // smem row
    int chb  = tid >> 7;             // 0/1; second pair via +2
    const char* pAhi = (const char*)Ahi + (size_t)(mBase + lrow) * (DIMC * 2);
    const char* pAlo = (const char*)Alo + (size_t)(mBase + lrow) * (DIMC * 2);
    const char* pBhi = (const char*)Bhi + (size_t)(nBase + lrow) * (DIMC * 2);
    const char* pBlo = (const char*)Blo + (size_t)(nBase + lrow) * (DIMC * 2);

    auto load_chunk = [&](int c, int s) {
        uint32_t stb = sb + s * STAGE + lrow * ROWB;
        size_t ko = (size_t)c * (BK * 2);
        #pragma unroll
        for (int i = 0; i < 2; i++) {
            int ch = chb + 2 * i;
            uint32_t d = stb + ch * 16;
            size_t so = ko + ch * 16;
            cp16(d,            pAhi + so);
            cp16(d + MATB,     pAlo + so);
            cp16(d + 2 * MATB, pBhi + so);
            cp16(d + 3 * MATB, pBlo + so);
        }
    };

    float acc[4][4][4];
    #pragma unroll
    for (int a = 0; a < 4; a++)
        #pragma unroll
        for (int b = 0; b < 4; b++)
            #pragma unroll
            for (int d = 0; d < 4; d++) acc[a][b][d] = 0.f;

    int wm = (wid >> 2) * 64;        // warp m offset in tile
    int wn = (wid & 3) * 32;         // warp n offset

    // ldmatrix lane offsets
    uint32_t aLaneOff = (uint32_t)((lane & 15) * ROWB + (lane >> 4) * 16);
    uint32_t bLaneOff = (uint32_t)((((lane & 7) + ((lane >> 4) << 3)) * ROWB)
                                   + (((lane >> 3) & 1) * 16));

    load_chunk(0, 0);
    asm volatile("cp.async.commit_group;");

    for (int c = 0; c < NCHUNK; c++) {
        int s = c & 1;
        if (c + 1 < NCHUNK) {
            load_chunk(c + 1, s ^ 1);
            asm volatile("cp.async.commit_group;");
            asm volatile("cp.async.wait_group 1;" ::: "memory");
        } else {
            asm volatile("cp.async.wait_group 0;" ::: "memory");
        }
        __syncthreads();

        uint32_t stb = sb + s * STAGE;
        #pragma unroll
        for (int ks = 0; ks < 2; ks++) {
            uint32_t kbB = ks * 32;  // 16 fp16 = 32 bytes
            uint32_t bh[2][4], bl[2][4];
            #pragma unroll
            for (int p = 0; p < 2; p++) {
                uint32_t ba = stb + 2 * MATB + (wn + p * 16) * ROWB + kbB + bLaneOff;
                ldsm4(bh[p], ba);
                ldsm4(bl[p], ba + MATB);
            }
            #pragma unroll
            for (int mt = 0; mt < 4; mt++) {
                uint32_t aa = stb + (wm + mt * 16) * ROWB + kbB + aLaneOff;
                uint32_t ah[4], al[4];
                ldsm4(ah, aa);
                ldsm4(al, aa + MATB);
                #pragma unroll
                for (int p = 0; p < 2; p++) {
                    mma16816(acc[mt][2*p],     ah, bh[p][0], bh[p][1]);
                    mma16816(acc[mt][2*p],     ah, bl[p][0], bl[p][1]);
                    mma16816(acc[mt][2*p],     al, bh[p][0], bh[p][1]);
                    mma16816(acc[mt][2*p + 1], ah, bh[p][2], bh[p][3]);
                    mma16816(acc[mt][2*p + 1], ah, bl[p][2], bl[p][3]);
                    mma16816(acc[mt][2*p + 1], al, bh[p][2], bh[p][3]);
                }
            }
        }
        __syncthreads();
    }

    // epilogue: c-frag (mt, nt): {row, col}={l/4, 2(l%4)} and row+8
    #pragma unroll
    for (int mt = 0; mt < 4; mt++) {
        #pragma unroll
        for (int nt = 0; nt < 4; nt++) {
            int row0 = mBase + wm + mt * 16 + (lane >> 2);
            int col  = nBase + wn + nt * 8 + (lane & 3) * 2;
            float2 v0 = make_float2(acc[mt][nt][0], acc[mt][nt][1]);
            float2 v1 = make_float2(acc[mt][nt][2], acc[mt][nt][3]);
            if (BIAS) {
                float2 bb = *(const float2*)(bias + col);
                v0.x += bb.x; v0.y += bb.y;
                v1.x += bb.x; v1.y += bb.y;
            }
            *(float2*)(C + (size_t)row0 * DIMC + col)       = v0;
            *(float2*)(C + (size_t)(row0 + 8) * DIMC + col) = v1;
        }
    }
}

// ---------------------------------------------------------------------------
// Flash attention (fp32 SIMT, proven in R1), writes fp16 hi/lo split output
// ---------------------------------------------------------------------------
__global__ void __launch_bounds__(256) attn_kernel(const float* __restrict__ q,
                                                   const float* __restrict__ k,
                                                   const float* __restrict__ v,
                                                   const float* __restrict__ alibi,
                                                   __half* __restrict__ ohi,
                                                   __half* __restrict__ olo) {
    extern __shared__ float smx[];
    float* Qs = smx;
    float* Ks = Qs + 64 * QS_STRIDE;
    float* Vs = Ks + 64 * QS_STRIDE;
    float* Ps = Vs + 64 * VS_STRIDE;

    int bh = blockIdx.y;
    int bi = bh >> 4;
    int h  = bh & 15;
    int i0 = blockIdx.x * 64;
    int tid = threadIdx.x;
    int ty = tid >> 4, tx = tid & 15;

    const float* qb = q + ((size_t)bi * SEQ + i0) * DIMC + h * DHEAD;
    #pragma unroll
    for (int u = 0; u < 4; u++) {
        int f = tid + 256 * u;
        int rr = f >> 4;
        int cc = (f & 15) << 2;
        float4 val = *(const float4*)(qb + (size_t)rr * DIMC + cc);
        Qs[rr * QS_STRIDE + cc + 0] = val.x;
        Qs[rr * QS_STRIDE + cc + 1] = val.y;
        Qs[rr * QS_STRIDE + cc + 2] = val.z;
        Qs[rr * QS_STRIDE + cc + 3] = val.w;
    }

    float m_i[4], l_i[4], acc[4][4];
    #pragma unroll
    for (int i = 0; i < 4; i++) {
        m_i[i] = -INFINITY; l_i[i] = 0.f;
        #pragma unroll
        for (int j = 0; j < 4; j++) acc[i][j] = 0.f;
    }

    const float* kb = k + (size_t)bi * SEQ * DIMC + h * DHEAD;
    const float* vb = v + (size_t)bi * SEQ * DIMC + h * DHEAD;

    for (int j0 = 0; j0 < SEQ; j0 += 64) {
        __syncthreads();
        #pragma unroll
        for (int u = 0; u < 4; u++) {
            int f = tid + 256 * u;
            int rr = f >> 4;
            int cc = (f & 15) << 2;
            float4 kv4 = *(const float4*)(kb + (size_t)(j0 + rr) * DIMC + cc);
            Ks[rr * QS_STRIDE + cc + 0] = kv4.x;
            Ks[rr * QS_STRIDE + cc + 1] = kv4.y;
            Ks[rr * QS_STRIDE + cc + 2] = kv4.z;
            Ks[rr * QS_STRIDE + cc + 3] = kv4.w;
            float4 vv4 = *(const float4*)(vb + (size_t)(j0 + rr) * DIMC + cc);
            *(float4*)&Vs[rr * VS_STRIDE + cc] = vv4;
        }
        __syncthreads();

        float s[4][4];
        #pragma unroll
        for (int i = 0; i < 4; i++)
            #pragma unroll
            for (int j = 0; j < 4; j++) s[i][j] = 0.f;
        #pragma unroll 8
        for (int kk = 0; kk < 64; kk++) {
            float qv[4], kv[4];
            #pragma unroll
            for (int i = 0; i < 4; i++) qv[i] = Qs[(ty * 4 + i) * QS_STRIDE + kk];
            #pragma unroll
            for (int j = 0; j < 4; j++) kv[j] = Ks[(tx * 4 + j) * QS_STRIDE + kk];
            #pragma unroll
            for (int i = 0; i < 4; i++)
                #pragma unroll
                for (int j = 0; j < 4; j++)
                    s[i][j] = fmaf(qv[i], kv[j], s[i][j]);
        }

        const float* ab = alibi + ((size_t)h * SEQ + i0 + ty * 4) * SEQ + j0 + tx * 4;
        #pragma unroll
        for (int i = 0; i < 4; i++) {
            float4 al = *(const float4*)(ab + (size_t)i * SEQ);
            s[i][0] = s[i][0] * ATT_SCALE + al.x;
            s[i][1] = s[i][1] * ATT_SCALE + al.y;
            s[i][2] = s[i][2] * ATT_SCALE + al.z;
            s[i][3] = s[i][3] * ATT_SCALE + al.w;
        }

        #pragma unroll
        for (int i = 0; i < 4; i++) {
            float rm = fmaxf(fmaxf(s[i][0], s[i][1]), fmaxf(s[i][2], s[i][3]));
            #pragma unroll
            for (int o = 8; o; o >>= 1)
                rm = fmaxf(rm, __shfl_xor_sync(0xffffffffu, rm, o));
            float mn = fmaxf(m_i[i], rm);
            float alpha = __expf(m_i[i] - mn);
            m_i[i] = mn;
            float rs = 0.f;
            #pragma unroll
            for (int j = 0; j < 4; j++) { s[i][j] = __expf(s[i][j] - mn); rs += s[i][j]; }
            #pragma unroll
            for (int o = 8; o; o >>= 1)
                rs += __shfl_xor_sync(0xffffffffu, rs, o);
            l_i[i] = l_i[i] * alpha + rs;
            #pragma unroll
            for (int j = 0; j < 4; j++) acc[i][j] *= alpha;
            *(float4*)&Ps[(ty * 4 + i) * VS_STRIDE + tx * 4] =
                make_float4(s[i][0], s[i][1], s[i][2], s[i][3]);
        }
        __syncthreads();

        #pragma unroll 8
        for (int j = 0; j < 64; j++) {
            float4 vv = *(const float4*)&Vs[j * VS_STRIDE + tx * 4];
            #pragma unroll
            for (int i = 0; i < 4; i++) {
                float pj = Ps[(ty * 4 + i) * VS_STRIDE + j];
                acc[i][0] = fmaf(pj, vv.x, acc[i][0]);
                acc[i][1] = fmaf(pj, vv.y, acc[i][1]);
                acc[i][2] = fmaf(pj, vv.z, acc[i][2]);
                acc[i][3] = fmaf(pj, vv.w, acc[i][3]);
            }
        }
    }

    #pragma unroll
    for (int i = 0; i < 4; i++) {
        float invl = 1.0f / l_i[i];
        size_t base = ((size_t)bi * SEQ + i0 + ty * 4 + i) * DIMC + h * DHEAD + tx * 4;
        float y[4];
        #pragma unroll
        for (int j = 0; j < 4; j++) y[j] = acc[i][j] * invl;
        __half hh[4], ll[4];
        #pragma unroll
        for (int j = 0; j < 4; j++) {
            hh[j] = __float2half_rn(y[j]);
            ll[j] = __float2half_rn(y[j] - __half2float(hh[j]));
        }
        *(__half2*)(ohi + base)     = __halves2half2(hh[0], hh[1]);
        *(__half2*)(ohi + base + 2) = __halves2half2(hh[2], hh[3]);
        *(__half2*)(olo + base)     = __halves2half2(ll[0], ll[1]);
        *(__half2*)(olo + base + 2) = __halves2half2(ll[2], ll[3]);
    }
}

// ---------------------------------------------------------------------------
extern "C" void kernel_launch(void* const* d_in, const int* in_sizes, int n_in,
                              void* d_out, int out_size) {
    const float* x     = (const float*)d_in[0];
    const float* ctx   = (const float*)d_in[1];
    const float* alibi = (const float*)d_in[2];
    const float* Wq    = (const float*)d_in[3];
    const float* Wk    = (const float*)d_in[4];
    const float* Wv    = (const float*)d_in[5];
    const float* Wo    = (const float*)d_in[6];
    const float* bo    = (const float*)d_in[7];
    const float* ln_w  = (const float*)d_in[8];
    const float* ln_b  = (const float*)d_in[9];
    float* out = (float*)d_out;

    __half *xhi, *xlo, *chi, *clo, *ahi, *alo, *wb;
    float *q, *k, *v;
    cudaGetSymbolAddress((void**)&xhi, g_xhi);
    cudaGetSymbolAddress((void**)&xlo, g_xlo);
    cudaGetSymbolAddress((void**)&chi, g_chi);
    cudaGetSymbolAddress((void**)&clo, g_clo);
    cudaGetSymbolAddress((void**)&ahi, g_ahi);
    cudaGetSymbolAddress((void**)&alo, g_alo);
    cudaGetSymbolAddress((void**)&wb,  g_wb);
    cudaGetSymbolAddress((void**)&q,   g_q);
    cudaGetSymbolAddress((void**)&k,   g_k);
    cudaGetSymbolAddress((void**)&v,   g_v);

    size_t wsz = (size_t)DIMC * DIMC;
    __half *wqh = wb,           *wql = wb + wsz;
    __half *wkh = wb + 2 * wsz, *wkl = wb + 3 * wsz;
    __half *wvh = wb + 4 * wsz, *wvl = wb + 5 * wsz;
    __half *woh = wb + 6 * wsz, *wol = wb + 7 * wsz;

    // LayerNorm -> fp16 splits
    ln_kernel<<<NROWS, 256>>>(x,   ln_w, ln_b, xhi, xlo);
    ln_kernel<<<NROWS, 256>>>(ctx, ln_w, ln_b, chi, clo);

    // weight splits
    int n4 = DIMC * DIMC / 4;
    split_kernel<<<n4 / 256, 256>>>((const float4*)Wq, wqh, wql, n4);
    split_kernel<<<n4 / 256, 256>>>((const float4*)Wk, wkh, wkl, n4);
    split_kernel<<<n4 / 256, 256>>>((const float4*)Wv, wvh, wvl, n4);
    split_kernel<<<n4 / 256, 256>>>((const float4*)Wo, woh, wol, n4);

    // mma.sync GEMMs
    cudaFuncSetAttribute(gemm_mma<false>, cudaFuncAttributeMaxDynamicSharedMemorySize, GSMEM);
    cudaFuncSetAttribute(gemm_mma<true>,  cudaFuncAttributeMaxDynamicSharedMemorySize, GSMEM);
    dim3 gg(DIMC / 128, NROWS / 128);
    gemm_mma<false><<<gg, 256, GSMEM>>>(xhi, xlo, wqh, wql, nullptr, q);
    gemm_mma<false><<<gg, 256, GSMEM>>>(chi, clo, wkh, wkl, nullptr, k);
    gemm_mma<false><<<gg, 256, GSMEM>>>(chi, clo, wvh, wvl, nullptr, v);

    // attention (fp32 SIMT) -> fp16 split output
    size_t smem = (size_t)(2 * 64 * QS_STRIDE + 2 * 64 * VS_STRIDE) * sizeof(float);
    cudaFuncSetAttribute(attn_kernel, cudaFuncAttributeMaxDynamicSharedMemorySize, (int)smem);
    dim3 ga(SEQ / 64, NB * NHEAD);
    attn_kernel<<<ga, 256, smem>>>(q, k, v, alibi, ahi, alo);

    // output projection
    gemm_mma<true><<<gg, 256, GSMEM>>>(ahi, alo, woh, wol, bo, out);
}

// round 8
// speedup vs baseline: 2.6556x; 1.9356x over previous
#include <cuda_runtime.h>
#include <cuda_fp16.h>
#include <math.h>
#include <stdint.h>

#define DIMC   1024
#define NHEAD  16
#define DHEAD  64
#define SEQ    2048
#define NB     2
#define NROWS  (NB * SEQ)       // 4096
#define ATT_SCALE 0.125f

// ---------------------------------------------------------------------------
// Scratch (device globals; no allocation allowed)
// ---------------------------------------------------------------------------
__device__ __half g_xhi[(size_t)NROWS * DIMC];
__device__ __half g_xlo[(size_t)NROWS * DIMC];
__device__ __half g_chi[(size_t)NROWS * DIMC];
__device__ __half g_clo[(size_t)NROWS * DIMC];
__device__ __half g_ahi[(size_t)NROWS * DIMC];
__device__ __half g_alo[(size_t)NROWS * DIMC];
__device__ __half g_wb[8ul * DIMC * DIMC];   // 4 weights x (hi,lo)
__device__ __half g_qh[(size_t)NROWS * DIMC];
__device__ __half g_kh[(size_t)NROWS * DIMC];
__device__ __half g_vh[(size_t)NROWS * DIMC];

// ---------------------------------------------------------------------------
// PTX helpers (sm_80 baseline only)
// ---------------------------------------------------------------------------
__device__ __forceinline__ uint32_t smem_u32(const void* p) {
    uint32_t a;
    asm("{ .reg .u64 t; cvta.to.shared.u64 t, %1; cvt.u32.u64 %0, t; }" : "=r"(a) : "l"(p));
    return a;
}
__device__ __forceinline__ void cp16(uint32_t dst, const void* src) {
    asm volatile("cp.async.cg.shared.global [%0], [%1], 16;" :: "r"(dst), "l"(src));
}
__device__ __forceinline__ void ldsm4(uint32_t* r, uint32_t addr) {
    asm volatile("ldmatrix.sync.aligned.m8n8.x4.shared.b16 {%0,%1,%2,%3}, [%4];"
        : "=r"(r[0]), "=r"(r[1]), "=r"(r[2]), "=r"(r[3]) : "r"(addr));
}
__device__ __forceinline__ void ldsm4t(uint32_t* r, uint32_t addr) {
    asm volatile("ldmatrix.sync.aligned.m8n8.x4.trans.shared.b16 {%0,%1,%2,%3}, [%4];"
        : "=r"(r[0]), "=r"(r[1]), "=r"(r[2]), "=r"(r[3]) : "r"(addr));
}
__device__ __forceinline__ void mma16816(float* c, const uint32_t* a,
                                         uint32_t b0, uint32_t b1) {
    asm volatile("mma.sync.aligned.m16n8k16.row.col.f32.f16.f16.f32 "
        "{%0,%1,%2,%3}, {%4,%5,%6,%7}, {%8,%9}, {%0,%1,%2,%3};"
        : "+f"(c[0]), "+f"(c[1]), "+f"(c[2]), "+f"(c[3])
        : "r"(a[0]), "r"(a[1]), "r"(a[2]), "r"(a[3]), "r"(b0), "r"(b1));
}
__device__ __forceinline__ uint32_t packh2(float a, float b) {
    __half2 h = __floats2half2_rn(a, b);
    return *(uint32_t*)&h;
}

// ---------------------------------------------------------------------------
// LayerNorm -> fp16 hi/lo split outputs
// ---------------------------------------------------------------------------
__global__ void __launch_bounds__(256) ln_kernel(const float* __restrict__ in,
                                                 const float* __restrict__ w,
                                                 const float* __restrict__ bvec,
                                                 __half* __restrict__ hi,
                                                 __half* __restrict__ lo) {
    int row = blockIdx.x;
    int t = threadIdx.x;
    const float4* rp = (const float4*)(in + (size_t)row * DIMC);
    float4 v = rp[t];
    float s  = v.x + v.y + v.z + v.w;
    float ss = v.x*v.x + v.y*v.y + v.z*v.z + v.w*v.w;

    __shared__ float s_sum[8], s_sq[8], s_stats[2];
    #pragma unroll
    for (int o = 16; o; o >>= 1) {
        s  += __shfl_xor_sync(0xffffffffu, s,  o);
        ss += __shfl_xor_sync(0xffffffffu, ss, o);
    }
    int lane = t & 31, wid = t >> 5;
    if (lane == 0) { s_sum[wid] = s; s_sq[wid] = ss; }
    __syncthreads();
    if (t == 0) {
        float a = 0.f, b2 = 0.f;
        #pragma unroll
        for (int i = 0; i < 8; i++) { a += s_sum[i]; b2 += s_sq[i]; }
        float mean = a * (1.0f / DIMC);
        float var  = b2 * (1.0f / DIMC) - mean * mean;
        s_stats[0] = mean;
        s_stats[1] = rsqrtf(var + 1e-5f);
    }
    __syncthreads();
    float mean = s_stats[0], inv = s_stats[1];
    float4 wv = ((const float4*)w)[t];
    float4 bv = ((const float4*)bvec)[t];
    float y[4];
    y[0] = (v.x - mean) * inv * wv.x + bv.x;
    y[1] = (v.y - mean) * inv * wv.y + bv.y;
    y[2] = (v.z - mean) * inv * wv.z + bv.z;
    y[3] = (v.w - mean) * inv * wv.w + bv.w;

    __half h[4], l[4];
    #pragma unroll
    for (int i = 0; i < 4; i++) {
        h[i] = __float2half_rn(y[i]);
        l[i] = __float2half_rn(y[i] - __half2float(h[i]));
    }
    size_t base = (size_t)row * DIMC + t * 4;
    *(__half2*)(hi + base)     = __halves2half2(h[0], h[1]);
    *(__half2*)(hi + base + 2) = __halves2half2(h[2], h[3]);
    *(__half2*)(lo + base)     = __halves2half2(l[0], l[1]);
    *(__half2*)(lo + base + 2) = __halves2half2(l[2], l[3]);
}

// Split a float matrix into fp16 hi/lo
__global__ void __launch_bounds__(256) split_kernel(const float4* __restrict__ in,
                                                    __half* __restrict__ hi,
                                                    __half* __restrict__ lo, int n4) {
    int i = blockIdx.x * blockDim.x + threadIdx.x;
    if (i >= n4) return;
    float4 v = in[i];
    float y[4] = {v.x, v.y, v.z, v.w};
    __half h[4], l[4];
    #pragma unroll
    for (int j = 0; j < 4; j++) {
        h[j] = __float2half_rn(y[j]);
        l[j] = __float2half_rn(y[j] - __half2float(h[j]));
    }
    size_t base = (size_t)i * 4;
    *(__half2*)(hi + base)     = __halves2half2(h[0], h[1]);
    *(__half2*)(hi + base + 2) = __halves2half2(h[2], h[3]);
    *(__half2*)(lo + base)     = __halves2half2(l[0], l[1]);
    *(__half2*)(lo + base + 2) = __halves2half2(l[2], l[3]);
}

// ---------------------------------------------------------------------------
// mma.sync fp16-split GEMM (validated R6). OUT=0: fp32 + bias; OUT=1: fp16.
// ---------------------------------------------------------------------------
#define BK        32
#define NCHUNK    (DIMC / BK)            // 32
#define ROWB      80
#define MATB      (128 * ROWB)
#define STAGE     (4 * MATB)
#define GSMEM     (2 * STAGE)            // 81920

template<int OUT>
__global__ void __launch_bounds__(256, 2) gemm_mma(
    const __half* __restrict__ Ahi, const __half* __restrict__ Alo,
    const __half* __restrict__ Bhi, const __half* __restrict__ Blo,
    const float* __restrict__ bias, void* __restrict__ Cv)
{
    extern __shared__ char smem[];
    uint32_t sb = smem_u32(smem);

    int tid = threadIdx.x, wid = tid >> 5, lane = tid & 31;
    int mBase = blockIdx.y * 128, nBase = blockIdx.x * 128;

    int lrow = tid & 127;
    int chb  = tid >> 7;
    const char* pAhi = (const char*)Ahi + (size_t)(mBase + lrow) * (DIMC * 2);
    const char* pAlo = (const char*)Alo + (size_t)(mBase + lrow) * (DIMC * 2);
    const char* pBhi = (const char*)Bhi + (size_t)(nBase + lrow) * (DIMC * 2);
    const char* pBlo = (const char*)Blo + (size_t)(nBase + lrow) * (DIMC * 2);

    auto load_chunk = [&](int c, int s) {
        uint32_t stb = sb + s * STAGE + lrow * ROWB;
        size_t ko = (size_t)c * (BK * 2);
        #pragma unroll
        for (int i = 0; i < 2; i++) {
            int ch = chb + 2 * i;
            uint32_t d = stb + ch * 16;
            size_t so = ko + ch * 16;
            cp16(d,            pAhi + so);
            cp16(d + MATB,     pAlo + so);
            cp16(d + 2 * MATB, pBhi + so);
            cp16(d + 3 * MATB, pBlo + so);
        }
    };

    float acc[4][4][4];
    #pragma unroll
    for (int a = 0; a < 4; a++)
        #pragma unroll
        for (int b = 0; b < 4; b++)
            #pragma unroll
            for (int d = 0; d < 4; d++) acc[a][b][d] = 0.f;

    int wm = (wid >> 2) * 64;
    int wn = (wid & 3) * 32;

    uint32_t aLaneOff = (uint32_t)((lane & 15) * ROWB + (lane >> 4) * 16);
    uint32_t bLaneOff = (uint32_t)((((lane & 7) + ((lane >> 4) << 3)) * ROWB)
                                   + (((lane >> 3) & 1) * 16));

    load_chunk(0, 0);
    asm volatile("cp.async.commit_group;");

    for (int c = 0; c < NCHUNK; c++) {
        int s = c & 1;
        if (c + 1 < NCHUNK) {
            load_chunk(c + 1, s ^ 1);
            asm volatile("cp.async.commit_group;");
            asm volatile("cp.async.wait_group 1;" ::: "memory");
        } else {
            asm volatile("cp.async.wait_group 0;" ::: "memory");
        }
        __syncthreads();

        uint32_t stb = sb + s * STAGE;
        #pragma unroll
        for (int ks = 0; ks < 2; ks++) {
            uint32_t kbB = ks * 32;
            uint32_t bh[2][4], bl[2][4];
            #pragma unroll
            for (int p = 0; p < 2; p++) {
                uint32_t ba = stb + 2 * MATB + (wn + p * 16) * ROWB + kbB + bLaneOff;
                ldsm4(bh[p], ba);
                ldsm4(bl[p], ba + MATB);
            }
            #pragma unroll
            for (int mt = 0; mt < 4; mt++) {
                uint32_t aa = stb + (wm + mt * 16) * ROWB + kbB + aLaneOff;
                uint32_t ah[4], al[4];
                ldsm4(ah, aa);
                ldsm4(al, aa + MATB);
                #pragma unroll
                for (int p = 0; p < 2; p++) {
                    mma16816(acc[mt][2*p],     ah, bh[p][0], bh[p][1]);
                    mma16816(acc[mt][2*p],     ah, bl[p][0], bl[p][1]);
                    mma16816(acc[mt][2*p],     al, bh[p][0], bh[p][1]);
                    mma16816(acc[mt][2*p + 1], ah, bh[p][2], bh[p][3]);
                    mma16816(acc[mt][2*p + 1], ah, bl[p][2], bl[p][3]);
                    mma16816(acc[mt][2*p + 1], al, bh[p][2], bh[p][3]);
                }
            }
        }
        __syncthreads();
    }

    #pragma unroll
    for (int mt = 0; mt < 4; mt++) {
        #pragma unroll
        for (int nt = 0; nt < 4; nt++) {
            int row0 = mBase + wm + mt * 16 + (lane >> 2);
            int col  = nBase + wn + nt * 8 + (lane & 3) * 2;
            if (OUT == 0) {
                float* C = (float*)Cv;
                float2 v0 = make_float2(acc[mt][nt][0], acc[mt][nt][1]);
                float2 v1 = make_float2(acc[mt][nt][2], acc[mt][nt][3]);
                float2 bb = *(const float2*)(bias + col);
                v0.x += bb.x; v0.y += bb.y;
                v1.x += bb.x; v1.y += bb.y;
                *(float2*)(C + (size_t)row0 * DIMC + col)       = v0;
                *(float2*)(C + (size_t)(row0 + 8) * DIMC + col) = v1;
            } else {
                __half* C = (__half*)Cv;
                *(__half2*)(C + (size_t)row0 * DIMC + col) =
                    __floats2half2_rn(acc[mt][nt][0], acc[mt][nt][1]);
                *(__half2*)(C + (size_t)(row0 + 8) * DIMC + col) =
                    __floats2half2_rn(acc[mt][nt][2], acc[mt][nt][3]);
            }
        }
    }
}

// ---------------------------------------------------------------------------
// Flash attention, mma.sync fp16.
// BM=64 (4 warps x m16), BN=64, Dh=64. K/V double-buffered via cp.async.
// Q/K/V smem rows: 72 halves (144B) -> conflict-free ldmatrix.
// P fragments converted C->A in registers; V loaded with ldmatrix.trans.
// ---------------------------------------------------------------------------
#define AROWB 144
#define QSM_BYTES (64 * AROWB)           // 9216
#define KVSTAGE   (2 * QSM_BYTES)        // K + V per stage
#define ASMEM     (QSM_BYTES + 2 * KVSTAGE)   // 46080

__global__ void __launch_bounds__(128) attn_kernel(const __half* __restrict__ q,
                                                   const __half* __restrict__ k,
                                                   const __half* __restrict__ v,
                                                   const float* __restrict__ alibi,
                                                   __half* __restrict__ ohi,
                                                   __half* __restrict__ olo) {
    extern __shared__ char smx[];
    uint32_t sq = smem_u32(smx);

    int bh = blockIdx.y;
    int bi = bh >> 4;
    int h  = bh & 15;
    int i0 = blockIdx.x * 64;
    int tid = threadIdx.x, wid = tid >> 5, lane = tid & 31;
    int wm = wid * 16;

    // gmem bases (head slice, fp16, row stride DIMC halves = 2048B)
    const char* qb = (const char*)(q + ((size_t)bi * SEQ + i0) * DIMC + h * DHEAD);
    const char* kb = (const char*)(k + ((size_t)bi * SEQ) * DIMC + h * DHEAD);
    const char* vb = (const char*)(v + ((size_t)bi * SEQ) * DIMC + h * DHEAD);

    // loader: thread t -> row t>>1, 4 chunks of 16B at (t&1)*64 + i*16
    int lr = tid >> 1;
    int lc = (tid & 1) * 64;
    uint32_t dOff = (uint32_t)(lr * AROWB + lc);
    size_t gOff = (size_t)lr * (DIMC * 2) + lc;

    // Q load (stage with first K/V group)
    #pragma unroll
    for (int i = 0; i < 4; i++) cp16(sq + dOff + i * 16, qb + gOff + i * 16);

    auto load_kv = [&](int j0, int s) {
        uint32_t ks_ = sq + QSM_BYTES + s * KVSTAGE;
        uint32_t vs_ = ks_ + QSM_BYTES;
        size_t g = gOff + (size_t)j0 * (DIMC * 2);
        #pragma unroll
        for (int i = 0; i < 4; i++) {
            cp16(ks_ + dOff + i * 16, kb + g + i * 16);
            cp16(vs_ + dOff + i * 16, vb + g + i * 16);
        }
    };

    load_kv(0, 0);
    asm volatile("cp.async.commit_group;");

    uint32_t aOff = (uint32_t)((lane & 15) * AROWB + (lane >> 4) * 16);
    uint32_t bOff = (uint32_t)((((lane & 7) + ((lane >> 4) << 3)) * AROWB)
                               + (((lane >> 3) & 1) * 16));

    float m0 = -INFINITY, m1 = -INFINITY, l0 = 0.f, l1 = 0.f;
    float o[8][4];
    #pragma unroll
    for (int nt = 0; nt < 8; nt++)
        #pragma unroll
        for (int c = 0; c < 4; c++) o[nt][c] = 0.f;

    const float* ab = alibi + ((size_t)h * SEQ + i0 + wm + (lane >> 2)) * SEQ + 2 * (lane & 3);

    for (int jt = 0; jt < SEQ / 64; jt++) {
        int s = jt & 1;
        if (jt + 1 < SEQ / 64) {
            load_kv((jt + 1) * 64, s ^ 1);
            asm volatile("cp.async.commit_group;");
            asm volatile("cp.async.wait_group 1;" ::: "memory");
        } else {
            asm volatile("cp.async.wait_group 0;" ::: "memory");
        }
        __syncthreads();

        uint32_t ksm = sq + QSM_BYTES + s * KVSTAGE;
        uint32_t vsm = ksm + QSM_BYTES;

        // S = Q K^T
        float sc[8][4];
        #pragma unroll
        for (int nt = 0; nt < 8; nt++)
            #pragma unroll
            for (int c = 0; c < 4; c++) sc[nt][c] = 0.f;
        #pragma unroll
        for (int kt = 0; kt < 4; kt++) {
            uint32_t a[4];
            ldsm4(a, sq + wm * AROWB + kt * 32 + aOff);
            #pragma unroll
            for (int p = 0; p < 4; p++) {
                uint32_t b[4];
                ldsm4(b, ksm + p * 16 * AROWB + kt * 32 + bOff);
                mma16816(sc[2*p],     a, b[0], b[1]);
                mma16816(sc[2*p + 1], a, b[2], b[3]);
            }
        }

        // scale + alibi
        int j0 = jt * 64;
        #pragma unroll
        for (int nt = 0; nt < 8; nt++) {
            float2 al0 = *(const float2*)(ab + j0 + nt * 8);
            float2 al1 = *(const float2*)(ab + 8 * SEQ + j0 + nt * 8);
            sc[nt][0] = fmaf(sc[nt][0], ATT_SCALE, al0.x);
            sc[nt][1] = fmaf(sc[nt][1], ATT_SCALE, al0.y);
            sc[nt][2] = fmaf(sc[nt][2], ATT_SCALE, al1.x);
            sc[nt][3] = fmaf(sc[nt][3], ATT_SCALE, al1.y);
        }

        // online softmax
        float mx0 = -INFINITY, mx1 = -INFINITY;
        #pragma unroll
        for (int nt = 0; nt < 8; nt++) {
            mx0 = fmaxf(mx0, fmaxf(sc[nt][0], sc[nt][1]));
            mx1 = fmaxf(mx1, fmaxf(sc[nt][2], sc[nt][3]));
        }
        mx0 = fmaxf(mx0, __shfl_xor_sync(0xffffffffu, mx0, 1));
        mx0 = fmaxf(mx0, __shfl_xor_sync(0xffffffffu, mx0, 2));
        mx1 = fmaxf(mx1, __shfl_xor_sync(0xffffffffu, mx1, 1));
        mx1 = fmaxf(mx1, __shfl_xor_sync(0xffffffffu, mx1, 2));

        float mn0 = fmaxf(m0, mx0), mn1 = fmaxf(m1, mx1);
        float alpha0 = __expf(m0 - mn0), alpha1 = __expf(m1 - mn1);
        m0 = mn0; m1 = mn1;

        float rs0 = 0.f, rs1 = 0.f;
        #pragma unroll
        for (int nt = 0; nt < 8; nt++) {
            sc[nt][0] = __expf(sc[nt][0] - mn0); rs0 += sc[nt][0];
            sc[nt][1] = __expf(sc[nt][1] - mn0); rs0 += sc[nt][1];
            sc[nt][2] = __expf(sc[nt][2] - mn1); rs1 += sc[nt][2];
            sc[nt][3] = __expf(sc[nt][3] - mn1); rs1 += sc[nt][3];
        }
        rs0 += __shfl_xor_sync(0xffffffffu, rs0, 1);
        rs0 += __shfl_xor_sync(0xffffffffu, rs0, 2);
        rs1 += __shfl_xor_sync(0xffffffffu, rs1, 1);
        rs1 += __shfl_xor_sync(0xffffffffu, rs1, 2);
        l0 = l0 * alpha0 + rs0;
        l1 = l1 * alpha1 + rs1;

        #pragma unroll
        for (int nt = 0; nt < 8; nt++) {
            o[nt][0] *= alpha0; o[nt][1] *= alpha0;
            o[nt][2] *= alpha1; o[nt][3] *= alpha1;
        }

        // O += P V  (P C-frags -> A-frags in registers; V via ldmatrix.trans)
        #pragma unroll
        for (int kt = 0; kt < 4; kt++) {
            uint32_t pa[4];
            pa[0] = packh2(sc[2*kt][0],     sc[2*kt][1]);
            pa[1] = packh2(sc[2*kt][2],     sc[2*kt][3]);
            pa[2] = packh2(sc[2*kt + 1][0], sc[2*kt + 1][1]);
            pa[3] = packh2(sc[2*kt + 1][2], sc[2*kt + 1][3]);
            #pragma unroll
            for (int dp = 0; dp < 4; dp++) {
                uint32_t vbf[4];
                ldsm4t(vbf, vsm + kt * 16 * AROWB + dp * 32 + aOff);
                mma16816(o[2*dp],     pa, vbf[0], vbf[1]);
                mma16816(o[2*dp + 1], pa, vbf[2], vbf[3]);
            }
        }
        __syncthreads();
    }

    // normalize + hi/lo split write
    float invl0 = 1.0f / l0, invl1 = 1.0f / l1;
    size_t r0 = (size_t)bi * SEQ + i0 + wm + (lane >> 2);
    int colb = h * DHEAD + 2 * (lane & 3);
    #pragma unroll
    for (int nt = 0; nt < 8; nt++) {
        float y0 = o[nt][0] * invl0, y1 = o[nt][1] * invl0;
        float y2 = o[nt][2] * invl1, y3 = o[nt][3] * invl1;
        __half h0 = __float2half_rn(y0), h1 = __float2half_rn(y1);
        __half h2 = __float2half_rn(y2), h3 = __float2half_rn(y3);
        size_t p0 = r0 * DIMC + colb + nt * 8;
        size_t p1 = (r0 + 8) * DIMC + colb + nt * 8;
        *(__half2*)(ohi + p0) = __halves2half2(h0, h1);
        *(__half2*)(ohi + p1) = __halves2half2(h2, h3);
        *(__half2*)(olo + p0) = __halves2half2(
            __float2half_rn(y0 - __half2float(h0)), __float2half_rn(y1 - __half2float(h1)));
        *(__half2*)(olo + p1) = __halves2half2(
            __float2half_rn(y2 - __half2float(h2)), __float2half_rn(y3 - __half2float(h3)));
    }
}

// ---------------------------------------------------------------------------
extern "C" void kernel_launch(void* const* d_in, const int* in_sizes, int n_in,
                              void* d_out, int out_size) {
    const float* x     = (const float*)d_in[0];
    const float* ctx   = (const float*)d_in[1];
    const float* alibi = (const float*)d_in[2];
    const float* Wq    = (const float*)d_in[3];
    const float* Wk    = (const float*)d_in[4];
    const float* Wv    = (const float*)d_in[5];
    const float* Wo    = (const float*)d_in[6];
    const float* bo    = (const float*)d_in[7];
    const float* ln_w  = (const float*)d_in[8];
    const float* ln_b  = (const float*)d_in[9];
    float* out = (float*)d_out;

    __half *xhi, *xlo, *chi, *clo, *ahi, *alo, *wb, *qh, *kh, *vh;
    cudaGetSymbolAddress((void**)&xhi, g_xhi);
    cudaGetSymbolAddress((void**)&xlo, g_xlo);
    cudaGetSymbolAddress((void**)&chi, g_chi);
    cudaGetSymbolAddress((void**)&clo, g_clo);
    cudaGetSymbolAddress((void**)&ahi, g_ahi);
    cudaGetSymbolAddress((void**)&alo, g_alo);
    cudaGetSymbolAddress((void**)&wb,  g_wb);
    cudaGetSymbolAddress((void**)&qh,  g_qh);
    cudaGetSymbolAddress((void**)&kh,  g_kh);
    cudaGetSymbolAddress((void**)&vh,  g_vh);

    size_t wsz = (size_t)DIMC * DIMC;
    __half *wqh = wb,           *wql = wb + wsz;
    __half *wkh = wb + 2 * wsz, *wkl = wb + 3 * wsz;
    __half *wvh = wb + 4 * wsz, *wvl = wb + 5 * wsz;
    __half *woh = wb + 6 * wsz, *wol = wb + 7 * wsz;

    ln_kernel<<<NROWS, 256>>>(x,   ln_w, ln_b, xhi, xlo);
    ln_kernel<<<NROWS, 256>>>(ctx, ln_w, ln_b, chi, clo);

    int n4 = DIMC * DIMC / 4;
    split_kernel<<<n4 / 256, 256>>>((const float4*)Wq, wqh, wql, n4);
    split_kernel<<<n4 / 256, 256>>>((const float4*)Wk, wkh, wkl, n4);
    split_kernel<<<n4 / 256, 256>>>((const float4*)Wv, wvh, wvl, n4);
    split_kernel<<<n4 / 256, 256>>>((const float4*)Wo, woh, wol, n4);

    cudaFuncSetAttribute(gemm_mma<0>, cudaFuncAttributeMaxDynamicSharedMemorySize, GSMEM);
    cudaFuncSetAttribute(gemm_mma<1>, cudaFuncAttributeMaxDynamicSharedMemorySize, GSMEM);
    dim3 gg(DIMC / 128, NROWS / 128);
    gemm_mma<1><<<gg, 256, GSMEM>>>(xhi, xlo, wqh, wql, nullptr, qh);
    gemm_mma<1><<<gg, 256, GSMEM>>>(chi, clo, wkh, wkl, nullptr, kh);
    gemm_mma<1><<<gg, 256, GSMEM>>>(chi, clo, wvh, wvl, nullptr, vh);

    cudaFuncSetAttribute(attn_kernel, cudaFuncAttributeMaxDynamicSharedMemorySize, ASMEM);
    dim3 ga(SEQ / 64, NB * NHEAD);
    attn_kernel<<<ga, 128, ASMEM>>>(qh, kh, vh, alibi, ahi, alo);

    gemm_mma<0><<<gg, 256, GSMEM>>>(ahi, alo, woh, wol, bo, out);
}

// round 9
// speedup vs baseline: 3.1032x; 1.1686x over previous
#include <cuda_runtime.h>
#include <cuda_fp16.h>
#include <math.h>
#include <stdint.h>

#define DIMC   1024
#define NHEAD  16
#define DHEAD  64
#define SEQ    2048
#define NB     2
#define NROWS  (NB * SEQ)       // 4096
#define ATT_SCALE 0.125f

// ---------------------------------------------------------------------------
// Scratch (device globals; no allocation allowed)
// ---------------------------------------------------------------------------
__device__ __half g_xhi[(size_t)NROWS * DIMC];
__device__ __half g_xlo[(size_t)NROWS * DIMC];
__device__ __half g_chi[(size_t)NROWS * DIMC];
__device__ __half g_clo[(size_t)NROWS * DIMC];
__device__ __half g_ahi[(size_t)NROWS * DIMC];
__device__ __half g_alo[(size_t)NROWS * DIMC];
__device__ __half g_wb[5ul * DIMC * DIMC];   // wq, wk, wv (hi only), wo hi, wo lo
__device__ __half g_qh[(size_t)NROWS * DIMC];
__device__ __half g_kh[(size_t)NROWS * DIMC];
__device__ __half g_vh[(size_t)NROWS * DIMC];

// ---------------------------------------------------------------------------
// PTX helpers (sm_80 baseline only)
// ---------------------------------------------------------------------------
__device__ __forceinline__ uint32_t smem_u32(const void* p) {
    uint32_t a;
    asm("{ .reg .u64 t; cvta.to.shared.u64 t, %1; cvt.u32.u64 %0, t; }" : "=r"(a) : "l"(p));
    return a;
}
__device__ __forceinline__ void cp16(uint32_t dst, const void* src) {
    asm volatile("cp.async.cg.shared.global [%0], [%1], 16;" :: "r"(dst), "l"(src));
}
__device__ __forceinline__ void ldsm4(uint32_t* r, uint32_t addr) {
    asm volatile("ldmatrix.sync.aligned.m8n8.x4.shared.b16 {%0,%1,%2,%3}, [%4];"
        : "=r"(r[0]), "=r"(r[1]), "=r"(r[2]), "=r"(r[3]) : "r"(addr));
}
__device__ __forceinline__ void ldsm4t(uint32_t* r, uint32_t addr) {
    asm volatile("ldmatrix.sync.aligned.m8n8.x4.trans.shared.b16 {%0,%1,%2,%3}, [%4];"
        : "=r"(r[0]), "=r"(r[1]), "=r"(r[2]), "=r"(r[3]) : "r"(addr));
}
__device__ __forceinline__ void mma16816(float* c, const uint32_t* a,
                                         uint32_t b0, uint32_t b1) {
    asm volatile("mma.sync.aligned.m16n8k16.row.col.f32.f16.f16.f32 "
        "{%0,%1,%2,%3}, {%4,%5,%6,%7}, {%8,%9}, {%0,%1,%2,%3};"
        : "+f"(c[0]), "+f"(c[1]), "+f"(c[2]), "+f"(c[3])
        : "r"(a[0]), "r"(a[1]), "r"(a[2]), "r"(a[3]), "r"(b0), "r"(b1));
}
__device__ __forceinline__ uint32_t packh2(float a, float b) {
    __half2 h = __floats2half2_rn(a, b);
    return *(uint32_t*)&h;
}

// ---------------------------------------------------------------------------
// LayerNorm -> fp16 hi/lo split outputs
// ---------------------------------------------------------------------------
__global__ void __launch_bounds__(256) ln_kernel(const float* __restrict__ in,
                                                 const float* __restrict__ w,
                                                 const float* __restrict__ bvec,
                                                 __half* __restrict__ hi,
                                                 __half* __restrict__ lo) {
    int row = blockIdx.x;
    int t = threadIdx.x;
    const float4* rp = (const float4*)(in + (size_t)row * DIMC);
    float4 v = rp[t];
    float s  = v.x + v.y + v.z + v.w;
    float ss = v.x*v.x + v.y*v.y + v.z*v.z + v.w*v.w;

    __shared__ float s_sum[8], s_sq[8], s_stats[2];
    #pragma unroll
    for (int o = 16; o; o >>= 1) {
        s  += __shfl_xor_sync(0xffffffffu, s,  o);
        ss += __shfl_xor_sync(0xffffffffu, ss, o);
    }
    int lane = t & 31, wid = t >> 5;
    if (lane == 0) { s_sum[wid] = s; s_sq[wid] = ss; }
    __syncthreads();
    if (t == 0) {
        float a = 0.f, b2 = 0.f;
        #pragma unroll
        for (int i = 0; i < 8; i++) { a += s_sum[i]; b2 += s_sq[i]; }
        float mean = a * (1.0f / DIMC);
        float var  = b2 * (1.0f / DIMC) - mean * mean;
        s_stats[0] = mean;
        s_stats[1] = rsqrtf(var + 1e-5f);
    }
    __syncthreads();
    float mean = s_stats[0], inv = s_stats[1];
    float4 wv = ((const float4*)w)[t];
    float4 bv = ((const float4*)bvec)[t];
    float y[4];
    y[0] = (v.x - mean) * inv * wv.x + bv.x;
    y[1] = (v.y - mean) * inv * wv.y + bv.y;
    y[2] = (v.z - mean) * inv * wv.z + bv.z;
    y[3] = (v.w - mean) * inv * wv.w + bv.w;

    __half h[4], l[4];
    #pragma unroll
    for (int i = 0; i < 4; i++) {
        h[i] = __float2half_rn(y[i]);
        l[i] = __float2half_rn(y[i] - __half2float(h[i]));
    }
    size_t base = (size_t)row * DIMC + t * 4;
    *(__half2*)(hi + base)     = __halves2half2(h[0], h[1]);
    *(__half2*)(hi + base + 2) = __halves2half2(h[2], h[3]);
    *(__half2*)(lo + base)     = __halves2half2(l[0], l[1]);
    *(__half2*)(lo + base + 2) = __halves2half2(l[2], l[3]);
}

// Split a float matrix into fp16 hi/lo (lo optional)
__global__ void __launch_bounds__(256) split_kernel(const float4* __restrict__ in,
                                                    __half* __restrict__ hi,
                                                    __half* __restrict__ lo, int n4) {
    int i = blockIdx.x * blockDim.x + threadIdx.x;
    if (i >= n4) return;
    float4 v = in[i];
    float y[4] = {v.x, v.y, v.z, v.w};
    __half h[4];
    #pragma unroll
    for (int j = 0; j < 4; j++) h[j] = __float2half_rn(y[j]);
    size_t base = (size_t)i * 4;
    *(__half2*)(hi + base)     = __halves2half2(h[0], h[1]);
    *(__half2*)(hi + base + 2) = __halves2half2(h[2], h[3]);
    if (lo) {
        __half l[4];
        #pragma unroll
        for (int j = 0; j < 4; j++) l[j] = __float2half_rn(y[j] - __half2float(h[j]));
        *(__half2*)(lo + base)     = __halves2half2(l[0], l[1]);
        *(__half2*)(lo + base + 2) = __halves2half2(l[2], l[3]);
    }
}

// ---------------------------------------------------------------------------
// mma.sync fp16-split GEMM core. PASSES=3: Ah*Bh + Ah*Bl + Al*Bh (Blo loaded)
//                                 PASSES=2: Ah*Bh + Al*Bh (B fp16-only)
// OUT=0: fp32 + bias; OUT=1: fp16.
// ---------------------------------------------------------------------------
#define BK        32
#define NCHUNK    (DIMC / BK)            // 32
#define ROWB      80
#define MATB      (128 * ROWB)
#define GSMEM2    (2 * 3 * MATB)         // 61440 (2-pass)
#define GSMEM3    (2 * 4 * MATB)         // 81920 (3-pass)

template<int PASSES, int OUT>
__device__ __forceinline__ void gemm_core(
    const __half* __restrict__ Ahi, const __half* __restrict__ Alo,
    const __half* __restrict__ Bhi, const __half* __restrict__ Blo,
    const float* __restrict__ bias, void* __restrict__ Cv,
    int mBase, int nBase)
{
    extern __shared__ char smem[];
    uint32_t sb = smem_u32(smem);
    const int NMAT = (PASSES == 3) ? 4 : 3;
    const uint32_t STG = NMAT * MATB;

    int tid = threadIdx.x, wid = tid >> 5, lane = tid & 31;

    int lrow = tid & 127;
    int chb  = tid >> 7;
    const char* pAhi = (const char*)Ahi + (size_t)(mBase + lrow) * (DIMC * 2);
    const char* pAlo = (const char*)Alo + (size_t)(mBase + lrow) * (DIMC * 2);
    const char* pBhi = (const char*)Bhi + (size_t)(nBase + lrow) * (DIMC * 2);
    const char* pBlo = (PASSES == 3) ? (const char*)Blo + (size_t)(nBase + lrow) * (DIMC * 2)
                                     : nullptr;

    auto load_chunk = [&](int c, int s) {
        uint32_t stb = sb + s * STG + lrow * ROWB;
        size_t ko = (size_t)c * (BK * 2);
        #pragma unroll
        for (int i = 0; i < 2; i++) {
            int ch = chb + 2 * i;
            uint32_t d = stb + ch * 16;
            size_t so = ko + ch * 16;
            cp16(d,            pAhi + so);
            cp16(d + MATB,     pAlo + so);
            cp16(d + 2 * MATB, pBhi + so);
            if (PASSES == 3) cp16(d + 3 * MATB, pBlo + so);
        }
    };

    float acc[4][4][4];
    #pragma unroll
    for (int a = 0; a < 4; a++)
        #pragma unroll
        for (int b = 0; b < 4; b++)
            #pragma unroll
            for (int d = 0; d < 4; d++) acc[a][b][d] = 0.f;

    int wm = (wid >> 2) * 64;
    int wn = (wid & 3) * 32;

    uint32_t aLaneOff = (uint32_t)((lane & 15) * ROWB + (lane >> 4) * 16);
    uint32_t bLaneOff = (uint32_t)((((lane & 7) + ((lane >> 4) << 3)) * ROWB)
                                   + (((lane >> 3) & 1) * 16));

    load_chunk(0, 0);
    asm volatile("cp.async.commit_group;");

    for (int c = 0; c < NCHUNK; c++) {
        int s = c & 1;
        if (c + 1 < NCHUNK) {
            load_chunk(c + 1, s ^ 1);
            asm volatile("cp.async.commit_group;");
            asm volatile("cp.async.wait_group 1;" ::: "memory");
        } else {
            asm volatile("cp.async.wait_group 0;" ::: "memory");
        }
        __syncthreads();

        uint32_t stb = sb + s * STG;
        #pragma unroll
        for (int ks = 0; ks < 2; ks++) {
            uint32_t kbB = ks * 32;
            uint32_t bh[2][4], bl[2][4];
            #pragma unroll
            for (int p = 0; p < 2; p++) {
                uint32_t ba = stb + 2 * MATB + (wn + p * 16) * ROWB + kbB + bLaneOff;
                ldsm4(bh[p], ba);
                if (PASSES == 3) ldsm4(bl[p], ba + MATB);
            }
            #pragma unroll
            for (int mt = 0; mt < 4; mt++) {
                uint32_t aa = stb + (wm + mt * 16) * ROWB + kbB + aLaneOff;
                uint32_t ah[4], al[4];
                ldsm4(ah, aa);
                ldsm4(al, aa + MATB);
                #pragma unroll
                for (int p = 0; p < 2; p++) {
                    mma16816(acc[mt][2*p],     ah, bh[p][0], bh[p][1]);
                    mma16816(acc[mt][2*p],     al, bh[p][0], bh[p][1]);
                    mma16816(acc[mt][2*p + 1], ah, bh[p][2], bh[p][3]);
                    mma16816(acc[mt][2*p + 1], al, bh[p][2], bh[p][3]);
                    if (PASSES == 3) {
                        mma16816(acc[mt][2*p],     ah, bl[p][0], bl[p][1]);
                        mma16816(acc[mt][2*p + 1], ah, bl[p][2], bl[p][3]);
                    }
                }
            }
        }
        __syncthreads();
    }

    #pragma unroll
    for (int mt = 0; mt < 4; mt++) {
        #pragma unroll
        for (int nt = 0; nt < 4; nt++) {
            int row0 = mBase + wm + mt * 16 + (lane >> 2);
            int col  = nBase + wn + nt * 8 + (lane & 3) * 2;
            if (OUT == 0) {
                float* C = (float*)Cv;
                float2 v0 = make_float2(acc[mt][nt][0], acc[mt][nt][1]);
                float2 v1 = make_float2(acc[mt][nt][2], acc[mt][nt][3]);
                float2 bb = *(const float2*)(bias + col);
                v0.x += bb.x; v0.y += bb.y;
                v1.x += bb.x; v1.y += bb.y;
                *(float2*)(C + (size_t)row0 * DIMC + col)       = v0;
                *(float2*)(C + (size_t)(row0 + 8) * DIMC + col) = v1;
            } else {
                __half* C = (__half*)Cv;
                *(__half2*)(C + (size_t)row0 * DIMC + col) =
                    __floats2half2_rn(acc[mt][nt][0], acc[mt][nt][1]);
                *(__half2*)(C + (size_t)(row0 + 8) * DIMC + col) =
                    __floats2half2_rn(acc[mt][nt][2], acc[mt][nt][3]);
            }
        }
    }
}

// Merged QKV: blockIdx.z selects {A, B, C}; 2-pass, fp16 out.
__global__ void __launch_bounds__(256, 2) qkv_gemm(
    const __half* __restrict__ xhi, const __half* __restrict__ xlo,
    const __half* __restrict__ chi, const __half* __restrict__ clo,
    const __half* __restrict__ wq, const __half* __restrict__ wk,
    const __half* __restrict__ wv,
    __half* __restrict__ qh, __half* __restrict__ kh, __half* __restrict__ vh)
{
    int z = blockIdx.z;
    const __half* Ahi = (z == 0) ? xhi : chi;
    const __half* Alo = (z == 0) ? xlo : clo;
    const __half* B   = (z == 0) ? wq : (z == 1) ? wk : wv;
    __half* C         = (z == 0) ? qh : (z == 1) ? kh : vh;
    gemm_core<2, 1>(Ahi, Alo, B, nullptr, nullptr, C,
                    blockIdx.y * 128, blockIdx.x * 128);
}

// Output projection: 3-pass, fp32 + bias.
__global__ void __launch_bounds__(256, 2) wo_gemm(
    const __half* __restrict__ Ahi, const __half* __restrict__ Alo,
    const __half* __restrict__ Bhi, const __half* __restrict__ Blo,
    const float* __restrict__ bias, float* __restrict__ C)
{
    gemm_core<3, 0>(Ahi, Alo, Bhi, Blo, bias, C, blockIdx.y * 128, blockIdx.x * 128);
}

// ---------------------------------------------------------------------------
// Flash attention, mma.sync fp16 (validated R8).
// ---------------------------------------------------------------------------
#define AROWB 144
#define QSM_BYTES (64 * AROWB)           // 9216
#define KVSTAGE   (2 * QSM_BYTES)
#define ASMEM     (QSM_BYTES + 2 * KVSTAGE)   // 46080

__global__ void __launch_bounds__(128) attn_kernel(const __half* __restrict__ q,
                                                   const __half* __restrict__ k,
                                                   const __half* __restrict__ v,
                                                   const float* __restrict__ alibi,
                                                   __half* __restrict__ ohi,
                                                   __half* __restrict__ olo) {
    extern __shared__ char smx[];
    uint32_t sq = smem_u32(smx);

    int bh = blockIdx.y;
    int bi = bh >> 4;
    int h  = bh & 15;
    int i0 = blockIdx.x * 64;
    int tid = threadIdx.x, wid = tid >> 5, lane = tid & 31;
    int wm = wid * 16;

    const char* qb = (const char*)(q + ((size_t)bi * SEQ + i0) * DIMC + h * DHEAD);
    const char* kb = (const char*)(k + ((size_t)bi * SEQ) * DIMC + h * DHEAD);
    const char* vb = (const char*)(v + ((size_t)bi * SEQ) * DIMC + h * DHEAD);

    int lr = tid >> 1;
    int lc = (tid & 1) * 64;
    uint32_t dOff = (uint32_t)(lr * AROWB + lc);
    size_t gOff = (size_t)lr * (DIMC * 2) + lc;

    #pragma unroll
    for (int i = 0; i < 4; i++) cp16(sq + dOff + i * 16, qb + gOff + i * 16);

    auto load_kv = [&](int j0, int s) {
        uint32_t ks_ = sq + QSM_BYTES + s * KVSTAGE;
        uint32_t vs_ = ks_ + QSM_BYTES;
        size_t g = gOff + (size_t)j0 * (DIMC * 2);
        #pragma unroll
        for (int i = 0; i < 4; i++) {
            cp16(ks_ + dOff + i * 16, kb + g + i * 16);
            cp16(vs_ + dOff + i * 16, vb + g + i * 16);
        }
    };

    load_kv(0, 0);
    asm volatile("cp.async.commit_group;");

    uint32_t aOff = (uint32_t)((lane & 15) * AROWB + (lane >> 4) * 16);
    uint32_t bOff = (uint32_t)((((lane & 7) + ((lane >> 4) << 3)) * AROWB)
                               + (((lane >> 3) & 1) * 16));

    float m0 = -INFINITY, m1 = -INFINITY, l0 = 0.f, l1 = 0.f;
    float o[8][4];
    #pragma unroll
    for (int nt = 0; nt < 8; nt++)
        #pragma unroll
        for (int c = 0; c < 4; c++) o[nt][c] = 0.f;

    const float* ab = alibi + ((size_t)h * SEQ + i0 + wm + (lane >> 2)) * SEQ + 2 * (lane & 3);

    for (int jt = 0; jt < SEQ / 64; jt++) {
        int s = jt & 1;
        if (jt + 1 < SEQ / 64) {
            load_kv((jt + 1) * 64, s ^ 1);
            asm volatile("cp.async.commit_group;");
            asm volatile("cp.async.wait_group 1;" ::: "memory");
        } else {
            asm volatile("cp.async.wait_group 0;" ::: "memory");
        }
        __syncthreads();

        uint32_t ksm = sq + QSM_BYTES + s * KVSTAGE;
        uint32_t vsm = ksm + QSM_BYTES;

        float sc[8][4];
        #pragma unroll
        for (int nt = 0; nt < 8; nt++)
            #pragma unroll
            for (int c = 0; c < 4; c++) sc[nt][c] = 0.f;
        #pragma unroll
        for (int kt = 0; kt < 4; kt++) {
            uint32_t a[4];
            ldsm4(a, sq + wm * AROWB + kt * 32 + aOff);
            #pragma unroll
            for (int p = 0; p < 4; p++) {
                uint32_t b[4];
                ldsm4(b, ksm + p * 16 * AROWB + kt * 32 + bOff);
                mma16816(sc[2*p],     a, b[0], b[1]);
                mma16816(sc[2*p + 1], a, b[2], b[3]);
            }
        }

        int j0 = jt * 64;
        #pragma unroll
        for (int nt = 0; nt < 8; nt++) {
            float2 al0 = *(const float2*)(ab + j0 + nt * 8);
            float2 al1 = *(const float2*)(ab + 8 * SEQ + j0 + nt * 8);
            sc[nt][0] = fmaf(sc[nt][0], ATT_SCALE, al0.x);
            sc[nt][1] = fmaf(sc[nt][1], ATT_SCALE, al0.y);
            sc[nt][2] = fmaf(sc[nt][2], ATT_SCALE, al1.x);
            sc[nt][3] = fmaf(sc[nt][3], ATT_SCALE, al1.y);
        }

        float mx0 = -INFINITY, mx1 = -INFINITY;
        #pragma unroll
        for (int nt = 0; nt < 8; nt++) {
            mx0 = fmaxf(mx0, fmaxf(sc[nt][0], sc[nt][1]));
            mx1 = fmaxf(mx1, fmaxf(sc[nt][2], sc[nt][3]));
        }
        mx0 = fmaxf(mx0, __shfl_xor_sync(0xffffffffu, mx0, 1));
        mx0 = fmaxf(mx0, __shfl_xor_sync(0xffffffffu, mx0, 2));
        mx1 = fmaxf(mx1, __shfl_xor_sync(0xffffffffu, mx1, 1));
        mx1 = fmaxf(mx1, __shfl_xor_sync(0xffffffffu, mx1, 2));

        float mn0 = fmaxf(m0, mx0), mn1 = fmaxf(m1, mx1);
        float alpha0 = __expf(m0 - mn0), alpha1 = __expf(m1 - mn1);
        m0 = mn0; m1 = mn1;

        float rs0 = 0.f, rs1 = 0.f;
        #pragma unroll
        for (int nt = 0; nt < 8; nt++) {
            sc[nt][0] = __expf(sc[nt][0] - mn0); rs0 += sc[nt][0];
            sc[nt][1] = __expf(sc[nt][1] - mn0); rs0 += sc[nt][1];
            sc[nt][2] = __expf(sc[nt][2] - mn1); rs1 += sc[nt][2];
            sc[nt][3] = __expf(sc[nt][3] - mn1); rs1 += sc[nt][3];
        }
        rs0 += __shfl_xor_sync(0xffffffffu, rs0, 1);
        rs0 += __shfl_xor_sync(0xffffffffu, rs0, 2);
        rs1 += __shfl_xor_sync(0xffffffffu, rs1, 1);
        rs1 += __shfl_xor_sync(0xffffffffu, rs1, 2);
        l0 = l0 * alpha0 + rs0;
        l1 = l1 * alpha1 + rs1;

        #pragma unroll
        for (int nt = 0; nt < 8; nt++) {
            o[nt][0] *= alpha0; o[nt][1] *= alpha0;
            o[nt][2] *= alpha1; o[nt][3] *= alpha1;
        }

        #pragma unroll
        for (int kt = 0; kt < 4; kt++) {
            uint32_t pa[4];
            pa[0] = packh2(sc[2*kt][0],     sc[2*kt][1]);
            pa[1] = packh2(sc[2*kt][2],     sc[2*kt][3]);
            pa[2] = packh2(sc[2*kt + 1][0], sc[2*kt + 1][1]);
            pa[3] = packh2(sc[2*kt + 1][2], sc[2*kt + 1][3]);
            #pragma unroll
            for (int dp = 0; dp < 4; dp++) {
                uint32_t vbf[4];
                ldsm4t(vbf, vsm + kt * 16 * AROWB + dp * 32 + aOff);
                mma16816(o[2*dp],     pa, vbf[0], vbf[1]);
                mma16816(o[2*dp + 1], pa, vbf[2], vbf[3]);
            }
        }
        __syncthreads();
    }

    float invl0 = 1.0f / l0, invl1 = 1.0f / l1;
    size_t r0 = (size_t)bi * SEQ + i0 + wm + (lane >> 2);
    int colb = h * DHEAD + 2 * (lane & 3);
    #pragma unroll
    for (int nt = 0; nt < 8; nt++) {
        float y0 = o[nt][0] * invl0, y1 = o[nt][1] * invl0;
        float y2 = o[nt][2] * invl1, y3 = o[nt][3] * invl1;
        __half h0 = __float2half_rn(y0), h1 = __float2half_rn(y1);
        __half h2 = __float2half_rn(y2), h3 = __float2half_rn(y3);
        size_t p0 = r0 * DIMC + colb + nt * 8;
        size_t p1 = (r0 + 8) * DIMC + colb + nt * 8;
        *(__half2*)(ohi + p0) = __halves2half2(h0, h1);
        *(__half2*)(ohi + p1) = __halves2half2(h2, h3);
        *(__half2*)(olo + p0) = __halves2half2(
            __float2half_rn(y0 - __half2float(h0)), __float2half_rn(y1 - __half2float(h1)));
        *(__half2*)(olo + p1) = __halves2half2(
            __float2half_rn(y2 - __half2float(h2)), __float2half_rn(y3 - __half2float(h3)));
    }
}

// ---------------------------------------------------------------------------
extern "C" void kernel_launch(void* const* d_in, const int* in_sizes, int n_in,
                              void* d_out, int out_size) {
    const float* x     = (const float*)d_in[0];
    const float* ctx   = (const float*)d_in[1];
    const float* alibi = (const float*)d_in[2];
    const float* Wq    = (const float*)d_in[3];
    const float* Wk    = (const float*)d_in[4];
    const float* Wv    = (const float*)d_in[5];
    const float* Wo    = (const float*)d_in[6];
    const float* bo    = (const float*)d_in[7];
    const float* ln_w  = (const float*)d_in[8];
    const float* ln_b  = (const float*)d_in[9];
    float* out = (float*)d_out;

    __half *xhi, *xlo, *chi, *clo, *ahi, *alo, *wb, *qh, *kh, *vh;
    cudaGetSymbolAddress((void**)&xhi, g_xhi);
    cudaGetSymbolAddress((void**)&xlo, g_xlo);
    cudaGetSymbolAddress((void**)&chi, g_chi);
    cudaGetSymbolAddress((void**)&clo, g_clo);
    cudaGetSymbolAddress((void**)&ahi, g_ahi);
    cudaGetSymbolAddress((void**)&alo, g_alo);
    cudaGetSymbolAddress((void**)&wb,  g_wb);
    cudaGetSymbolAddress((void**)&qh,  g_qh);
    cudaGetSymbolAddress((void**)&kh,  g_kh);
    cudaGetSymbolAddress((void**)&vh,  g_vh);

    size_t wsz = (size_t)DIMC * DIMC;
    __half *wq16 = wb;
    __half *wk16 = wb + wsz;
    __half *wv16 = wb + 2 * wsz;
    __half *woh  = wb + 3 * wsz;
    __half *wol  = wb + 4 * wsz;

    ln_kernel<<<NROWS, 256>>>(x,   ln_w, ln_b, xhi, xlo);
    ln_kernel<<<NROWS, 256>>>(ctx, ln_w, ln_b, chi, clo);

    int n4 = DIMC * DIMC / 4;
    split_kernel<<<n4 / 256, 256>>>((const float4*)Wq, wq16, nullptr, n4);
    split_kernel<<<n4 / 256, 256>>>((const float4*)Wk, wk16, nullptr, n4);
    split_kernel<<<n4 / 256, 256>>>((const float4*)Wv, wv16, nullptr, n4);
    split_kernel<<<n4 / 256, 256>>>((const float4*)Wo, woh, wol, n4);

    cudaFuncSetAttribute(qkv_gemm, cudaFuncAttributeMaxDynamicSharedMemorySize, GSMEM2);
    cudaFuncSetAttribute(wo_gemm,  cudaFuncAttributeMaxDynamicSharedMemorySize, GSMEM3);

    dim3 gq(DIMC / 128, NROWS / 128, 3);
    qkv_gemm<<<gq, 256, GSMEM2>>>(xhi, xlo, chi, clo, wq16, wk16, wv16, qh, kh, vh);

    cudaFuncSetAttribute(attn_kernel, cudaFuncAttributeMaxDynamicSharedMemorySize, ASMEM);
    dim3 ga(SEQ / 64, NB * NHEAD);
    attn_kernel<<<ga, 128, ASMEM>>>(qh, kh, vh, alibi, ahi, alo);

    dim3 gg(DIMC / 128, NROWS / 128);
    wo_gemm<<<gg, 256, GSMEM3>>>(ahi, alo, woh, wol, bo, out);
}

// round 11
// speedup vs baseline: 3.9524x; 1.2737x over previous
#include <cuda_runtime.h>
#include <cuda_fp16.h>
#include <math.h>
#include <stdint.h>

#define DIMC   1024
#define NHEAD  16
#define DHEAD  64
#define SEQ    2048
#define NB     2
#define NROWS  (NB * SEQ)       // 4096
#define ATT_SCALE 0.125f

// ---------------------------------------------------------------------------
// Scratch (device globals; no allocation allowed)
// ---------------------------------------------------------------------------
__device__ __half g_xhi[(size_t)NROWS * DIMC];
__device__ __half g_chi[(size_t)NROWS * DIMC];
__device__ __half g_ahi[(size_t)NROWS * DIMC];
__device__ __half g_alo[(size_t)NROWS * DIMC];
__device__ __half g_wb[4ul * DIMC * DIMC];   // wq, wk, wv, wo (fp16)
__device__ __half g_qh[(size_t)NROWS * DIMC];
__device__ __half g_kh[(size_t)NROWS * DIMC];
__device__ __half g_vh[(size_t)NROWS * DIMC];

// ---------------------------------------------------------------------------
// PTX helpers (sm_80 baseline only)
// ---------------------------------------------------------------------------
__device__ __forceinline__ uint32_t smem_u32(const void* p) {
    uint32_t a;
    asm("{ .reg .u64 t; cvta.to.shared.u64 t, %1; cvt.u32.u64 %0, t; }" : "=r"(a) : "l"(p));
    return a;
}
__device__ __forceinline__ void cp16(uint32_t dst, const void* src) {
    asm volatile("cp.async.cg.shared.global [%0], [%1], 16;" :: "r"(dst), "l"(src));
}
__device__ __forceinline__ void ldsm4(uint32_t* r, uint32_t addr) {
    asm volatile("ldmatrix.sync.aligned.m8n8.x4.shared.b16 {%0,%1,%2,%3}, [%4];"
        : "=r"(r[0]), "=r"(r[1]), "=r"(r[2]), "=r"(r[3]) : "r"(addr));
}
__device__ __forceinline__ void ldsm4t(uint32_t* r, uint32_t addr) {
    asm volatile("ldmatrix.sync.aligned.m8n8.x4.trans.shared.b16 {%0,%1,%2,%3}, [%4];"
        : "=r"(r[0]), "=r"(r[1]), "=r"(r[2]), "=r"(r[3]) : "r"(addr));
}
__device__ __forceinline__ void mma16816(float* c, const uint32_t* a,
                                         uint32_t b0, uint32_t b1) {
    asm volatile("mma.sync.aligned.m16n8k16.row.col.f32.f16.f16.f32 "
        "{%0,%1,%2,%3}, {%4,%5,%6,%7}, {%8,%9}, {%0,%1,%2,%3};"
        : "+f"(c[0]), "+f"(c[1]), "+f"(c[2]), "+f"(c[3])
        : "r"(a[0]), "r"(a[1]), "r"(a[2]), "r"(a[3]), "r"(b0), "r"(b1));
}
__device__ __forceinline__ uint32_t packh2(float a, float b) {
    __half2 h = __floats2half2_rn(a, b);
    return *(uint32_t*)&h;
}

// ---------------------------------------------------------------------------
// LayerNorm -> fp16 output (hi only; QKV GEMM is 1-pass)
// ---------------------------------------------------------------------------
__global__ void __launch_bounds__(256) ln_kernel(const float* __restrict__ in,
                                                 const float* __restrict__ w,
                                                 const float* __restrict__ bvec,
                                                 __half* __restrict__ hi) {
    int row = blockIdx.x;
    int t = threadIdx.x;
    const float4* rp = (const float4*)(in + (size_t)row * DIMC);
    float4 v = rp[t];
    float s  = v.x + v.y + v.z + v.w;
    float ss = v.x*v.x + v.y*v.y + v.z*v.z + v.w*v.w;

    __shared__ float s_sum[8], s_sq[8], s_stats[2];
    #pragma unroll
    for (int o = 16; o; o >>= 1) {
        s  += __shfl_xor_sync(0xffffffffu, s,  o);
        ss += __shfl_xor_sync(0xffffffffu, ss, o);
    }
    int lane = t & 31, wid = t >> 5;
    if (lane == 0) { s_sum[wid] = s; s_sq[wid] = ss; }
    __syncthreads();
    if (t == 0) {
        float a = 0.f, b2 = 0.f;
        #pragma unroll
        for (int i = 0; i < 8; i++) { a += s_sum[i]; b2 += s_sq[i]; }
        float mean = a * (1.0f / DIMC);
        float var  = b2 * (1.0f / DIMC) - mean * mean;
        s_stats[0] = mean;
        s_stats[1] = rsqrtf(var + 1e-5f);
    }
    __syncthreads();
    float mean = s_stats[0], inv = s_stats[1];
    float4 wv = ((const float4*)w)[t];
    float4 bv = ((const float4*)bvec)[t];
    __half h0 = __float2half_rn((v.x - mean) * inv * wv.x + bv.x);
    __half h1 = __float2half_rn((v.y - mean) * inv * wv.y + bv.y);
    __half h2 = __float2half_rn((v.z - mean) * inv * wv.z + bv.z);
    __half h3 = __float2half_rn((v.w - mean) * inv * wv.w + bv.w);
    size_t base = (size_t)row * DIMC + t * 4;
    *(__half2*)(hi + base)     = __halves2half2(h0, h1);
    *(__half2*)(hi + base + 2) = __halves2half2(h2, h3);
}

// Convert 4 float matrices to fp16 in one launch (y selects matrix)
__global__ void __launch_bounds__(256) cvt_kernel(const float4* __restrict__ w0,
                                                  const float4* __restrict__ w1,
                                                  const float4* __restrict__ w2,
                                                  const float4* __restrict__ w3,
                                                  __half* __restrict__ out, int n4) {
    int z = blockIdx.y;
    const float4* in = (z == 0) ? w0 : (z == 1) ? w1 : (z == 2) ? w2 : w3;
    int i = blockIdx.x * blockDim.x + threadIdx.x;
    if (i >= n4) return;
    float4 v = in[i];
    size_t base = (size_t)z * (DIMC * DIMC) + (size_t)i * 4;
    *(__half2*)(out + base)     = __floats2half2_rn(v.x, v.y);
    *(__half2*)(out + base + 2) = __floats2half2_rn(v.z, v.w);
}

// ---------------------------------------------------------------------------
// mma.sync GEMM core.
// PASSES=1: Ah*Bh                 (stage: A, B)
// PASSES=2: Ah*Bh + Al*Bh         (stage: A, Alo, B)
// OUT=0: fp32 + bias; OUT=1: fp16.
// ---------------------------------------------------------------------------
#define BK        32
#define NCHUNK    (DIMC / BK)            // 32
#define ROWB      80
#define MATB      (128 * ROWB)
#define GSMEM1    (2 * 2 * MATB)         // 40960 (1-pass)
#define GSMEM2    (2 * 3 * MATB)         // 61440 (2-pass)

template<int PASSES, int OUT>
__device__ __forceinline__ void gemm_core(
    const __half* __restrict__ Ahi, const __half* __restrict__ Alo,
    const __half* __restrict__ Bhi,
    const float* __restrict__ bias, void* __restrict__ Cv,
    int mBase, int nBase)
{
    extern __shared__ char smem[];
    uint32_t sb = smem_u32(smem);
    const int NA = (PASSES >= 2) ? 2 : 1;          // A matrices per stage
    const uint32_t BOFF = NA * MATB;               // B offset within stage
    const uint32_t STG = (NA + 1) * MATB;

    int tid = threadIdx.x, wid = tid >> 5, lane = tid & 31;

    int lrow = tid & 127;
    int chb  = tid >> 7;
    const char* pAhi = (const char*)Ahi + (size_t)(mBase + lrow) * (DIMC * 2);
    const char* pAlo = (PASSES >= 2) ? (const char*)Alo + (size_t)(mBase + lrow) * (DIMC * 2)
                                     : nullptr;
    const char* pBhi = (const char*)Bhi + (size_t)(nBase + lrow) * (DIMC * 2);

    auto load_chunk = [&](int c, int s) {
        uint32_t stb = sb + s * STG + lrow * ROWB;
        size_t ko = (size_t)c * (BK * 2);
        #pragma unroll
        for (int i = 0; i < 2; i++) {
            int ch = chb + 2 * i;
            uint32_t d = stb + ch * 16;
            size_t so = ko + ch * 16;
            cp16(d, pAhi + so);
            if (PASSES >= 2) cp16(d + MATB, pAlo + so);
            cp16(d + BOFF, pBhi + so);
        }
    };

    float acc[4][4][4];
    #pragma unroll
    for (int a = 0; a < 4; a++)
        #pragma unroll
        for (int b = 0; b < 4; b++)
            #pragma unroll
            for (int d = 0; d < 4; d++) acc[a][b][d] = 0.f;

    int wm = (wid >> 2) * 64;
    int wn = (wid & 3) * 32;

    uint32_t aLaneOff = (uint32_t)((lane & 15) * ROWB + (lane >> 4) * 16);
    uint32_t bLaneOff = (uint32_t)((((lane & 7) + ((lane >> 4) << 3)) * ROWB)
                                   + (((lane >> 3) & 1) * 16));

    load_chunk(0, 0);
    asm volatile("cp.async.commit_group;");

    for (int c = 0; c < NCHUNK; c++) {
        int s = c & 1;
        if (c + 1 < NCHUNK) {
            load_chunk(c + 1, s ^ 1);
            asm volatile("cp.async.commit_group;");
            asm volatile("cp.async.wait_group 1;" ::: "memory");
        } else {
            asm volatile("cp.async.wait_group 0;" ::: "memory");
        }
        __syncthreads();

        uint32_t stb = sb + s * STG;
        #pragma unroll
        for (int ks = 0; ks < 2; ks++) {
            uint32_t kbB = ks * 32;
            uint32_t bh[2][4];
            #pragma unroll
            for (int p = 0; p < 2; p++)
                ldsm4(bh[p], stb + BOFF + (wn + p * 16) * ROWB + kbB + bLaneOff);
            #pragma unroll
            for (int mt = 0; mt < 4; mt++) {
                uint32_t aa = stb + (wm + mt * 16) * ROWB + kbB + aLaneOff;
                uint32_t ah[4], al[4];
                ldsm4(ah, aa);
                if (PASSES >= 2) ldsm4(al, aa + MATB);
                #pragma unroll
                for (int p = 0; p < 2; p++) {
                    mma16816(acc[mt][2*p],     ah, bh[p][0], bh[p][1]);
                    mma16816(acc[mt][2*p + 1], ah, bh[p][2], bh[p][3]);
                    if (PASSES >= 2) {
                        mma16816(acc[mt][2*p],     al, bh[p][0], bh[p][1]);
                        mma16816(acc[mt][2*p + 1], al, bh[p][2], bh[p][3]);
                    }
                }
            }
        }
        __syncthreads();
    }

    #pragma unroll
    for (int mt = 0; mt < 4; mt++) {
        #pragma unroll
        for (int nt = 0; nt < 4; nt++) {
            int row0 = mBase + wm + mt * 16 + (lane >> 2);
            int col  = nBase + wn + nt * 8 + (lane & 3) * 2;
            if (OUT == 0) {
                float* C = (float*)Cv;
                float2 v0 = make_float2(acc[mt][nt][0], acc[mt][nt][1]);
                float2 v1 = make_float2(acc[mt][nt][2], acc[mt][nt][3]);
                float2 bb = *(const float2*)(bias + col);
                v0.x += bb.x; v0.y += bb.y;
                v1.x += bb.x; v1.y += bb.y;
                *(float2*)(C + (size_t)row0 * DIMC + col)       = v0;
                *(float2*)(C + (size_t)(row0 + 8) * DIMC + col) = v1;
            } else {
                __half* C = (__half*)Cv;
                *(__half2*)(C + (size_t)row0 * DIMC + col) =
                    __floats2half2_rn(acc[mt][nt][0], acc[mt][nt][1]);
                *(__half2*)(C + (size_t)(row0 + 8) * DIMC + col) =
                    __floats2half2_rn(acc[mt][nt][2], acc[mt][nt][3]);
            }
        }
    }
}

// Merged QKV: blockIdx.z selects operands; 1-pass fp16.
__global__ void __launch_bounds__(256, 2) qkv_gemm(
    const __half* __restrict__ xhi, const __half* __restrict__ chi,
    const __half* __restrict__ wq, const __half* __restrict__ wk,
    const __half* __restrict__ wv,
    __half* __restrict__ qh, __half* __restrict__ kh, __half* __restrict__ vh)
{
    int z = blockIdx.z;
    const __half* A = (z == 0) ? xhi : chi;
    const __half* B = (z == 0) ? wq : (z == 1) ? wk : wv;
    __half* C       = (z == 0) ? qh : (z == 1) ? kh : vh;
    gemm_core<1, 1>(A, nullptr, B, nullptr, C, blockIdx.y * 128, blockIdx.x * 128);
}

// Output projection: 2-pass (attention-output hi/lo), fp32 + bias.
__global__ void __launch_bounds__(256, 2) wo_gemm(
    const __half* __restrict__ Ahi, const __half* __restrict__ Alo,
    const __half* __restrict__ Bhi,
    const float* __restrict__ bias, float* __restrict__ C)
{
    gemm_core<2, 0>(Ahi, Alo, Bhi, bias, C, blockIdx.y * 128, blockIdx.x * 128);
}

// ---------------------------------------------------------------------------
// Flash attention, mma.sync fp16 (validated R8/R9).
// Grid y remap: h = bh >> 1, bi = bh & 1 so the two batches sharing an alibi
// tile are 32 block-ids apart -> co-resident -> alibi L2 reuse.
// ---------------------------------------------------------------------------
#define AROWB 144
#define QSM_BYTES (64 * AROWB)           // 9216
#define KVSTAGE   (2 * QSM_BYTES)
#define ASMEM     (QSM_BYTES + 2 * KVSTAGE)   // 46080

__global__ void __launch_bounds__(128) attn_kernel(const __half* __restrict__ q,
                                                   const __half* __restrict__ k,
                                                   const __half* __restrict__ v,
                                                   const float* __restrict__ alibi,
                                                   __half* __restrict__ ohi,
                                                   __half* __restrict__ olo) {
    extern __shared__ char smx[];
    uint32_t sq = smem_u32(smx);

    int bh = blockIdx.y;
    int h  = bh >> 1;
    int bi = bh & 1;
    int i0 = blockIdx.x * 64;
    int tid = threadIdx.x, wid = tid >> 5, lane = tid & 31;
    int wm = wid * 16;

    const char* qb = (const char*)(q + ((size_t)bi * SEQ + i0) * DIMC + h * DHEAD);
    const char* kb = (const char*)(k + ((size_t)bi * SEQ) * DIMC + h * DHEAD);
    const char* vb = (const char*)(v + ((size_t)bi * SEQ) * DIMC + h * DHEAD);

    int lr = tid >> 1;
    int lc = (tid & 1) * 64;
    uint32_t dOff = (uint32_t)(lr * AROWB + lc);
    size_t gOff = (size_t)lr * (DIMC * 2) + lc;

    #pragma unroll
    for (int i = 0; i < 4; i++) cp16(sq + dOff + i * 16, qb + gOff + i * 16);

    auto load_kv = [&](int j0, int s) {
        uint32_t ks_ = sq + QSM_BYTES + s * KVSTAGE;
        uint32_t vs_ = ks_ + QSM_BYTES;
        size_t g = gOff + (size_t)j0 * (DIMC * 2);
        #pragma unroll
        for (int i = 0; i < 4; i++) {
            cp16(ks_ + dOff + i * 16, kb + g + i * 16);
            cp16(vs_ + dOff + i * 16, vb + g + i * 16);
        }
    };

    load_kv(0, 0);
    asm volatile("cp.async.commit_group;");

    uint32_t aOff = (uint32_t)((lane & 15) * AROWB + (lane >> 4) * 16);
    uint32_t bOff = (uint32_t)((((lane & 7) + ((lane >> 4) << 3)) * AROWB)
                               + (((lane >> 3) & 1) * 16));

    float m0 = -INFINITY, m1 = -INFINITY, l0 = 0.f, l1 = 0.f;
    float o[8][4];
    #pragma unroll
    for (int nt = 0; nt < 8; nt++)
        #pragma unroll
        for (int c = 0; c < 4; c++) o[nt][c] = 0.f;

    const float* ab = alibi + ((size_t)h * SEQ + i0 + wm + (lane >> 2)) * SEQ + 2 * (lane & 3);

    for (int jt = 0; jt < SEQ / 64; jt++) {
        int s = jt & 1;
        if (jt + 1 < SEQ / 64) {
            load_kv((jt + 1) * 64, s ^ 1);
            asm volatile("cp.async.commit_group;");
            asm volatile("cp.async.wait_group 1;" ::: "memory");
        } else {
            asm volatile("cp.async.wait_group 0;" ::: "memory");
        }
        __syncthreads();

        uint32_t ksm = sq + QSM_BYTES + s * KVSTAGE;
        uint32_t vsm = ksm + QSM_BYTES;

        float sc[8][4];
        #pragma unroll
        for (int nt = 0; nt < 8; nt++)
            #pragma unroll
            for (int c = 0; c < 4; c++) sc[nt][c] = 0.f;
        #pragma unroll
        for (int kt = 0; kt < 4; kt++) {
            uint32_t a[4];
            ldsm4(a, sq + wm * AROWB + kt * 32 + aOff);
            #pragma unroll
            for (int p = 0; p < 4; p++) {
                uint32_t b[4];
                ldsm4(b, ksm + p * 16 * AROWB + kt * 32 + bOff);
                mma16816(sc[2*p],     a, b[0], b[1]);
                mma16816(sc[2*p + 1], a, b[2], b[3]);
            }
        }

        int j0 = jt * 64;
        #pragma unroll
        for (int nt = 0; nt < 8; nt++) {
            float2 al0 = *(const float2*)(ab + j0 + nt * 8);
            float2 al1 = *(const float2*)(ab + 8 * SEQ + j0 + nt * 8);
            sc[nt][0] = fmaf(sc[nt][0], ATT_SCALE, al0.x);
            sc[nt][1] = fmaf(sc[nt][1], ATT_SCALE, al0.y);
            sc[nt][2] = fmaf(sc[nt][2], ATT_SCALE, al1.x);
            sc[nt][3] = fmaf(sc[nt][3], ATT_SCALE, al1.y);
        }

        float mx0 = -INFINITY, mx1 = -INFINITY;
        #pragma unroll
        for (int nt = 0; nt < 8; nt++) {
            mx0 = fmaxf(mx0, fmaxf(sc[nt][0], sc[nt][1]));
            mx1 = fmaxf(mx1, fmaxf(sc[nt][2], sc[nt][3]));
        }
        mx0 = fmaxf(mx0, __shfl_xor_sync(0xffffffffu, mx0, 1));
        mx0 = fmaxf(mx0, __shfl_xor_sync(0xffffffffu, mx0, 2));
        mx1 = fmaxf(mx1, __shfl_xor_sync(0xffffffffu, mx1, 1));
        mx1 = fmaxf(mx1, __shfl_xor_sync(0xffffffffu, mx1, 2));

        float mn0 = fmaxf(m0, mx0), mn1 = fmaxf(m1, mx1);
        float alpha0 = __expf(m0 - mn0), alpha1 = __expf(m1 - mn1);
        m0 = mn0; m1 = mn1;

        float rs0 = 0.f, rs1 = 0.f;
        #pragma unroll
        for (int nt = 0; nt < 8; nt++) {
            sc[nt][0] = __expf(sc[nt][0] - mn0); rs0 += sc[nt][0];
            sc[nt][1] = __expf(sc[nt][1] - mn0); rs0 += sc[nt][1];
            sc[nt][2] = __expf(sc[nt][2] - mn1); rs1 += sc[nt][2];
            sc[nt][3] = __expf(sc[nt][3] - mn1); rs1 += sc[nt][3];
        }
        rs0 += __shfl_xor_sync(0xffffffffu, rs0, 1);
        rs0 += __shfl_xor_sync(0xffffffffu, rs0, 2);
        rs1 += __shfl_xor_sync(0xffffffffu, rs1, 1);
        rs1 += __shfl_xor_sync(0xffffffffu, rs1, 2);
        l0 = l0 * alpha0 + rs0;
        l1 = l1 * alpha1 + rs1;

        #pragma unroll
        for (int nt = 0; nt < 8; nt++) {
            o[nt][0] *= alpha0; o[nt][1] *= alpha0;
            o[nt][2] *= alpha1; o[nt][3] *= alpha1;
        }

        #pragma unroll
        for (int kt = 0; kt < 4; kt++) {
            uint32_t pa[4];
            pa[0] = packh2(sc[2*kt][0],     sc[2*kt][1]);
            pa[1] = packh2(sc[2*kt][2],     sc[2*kt][3]);
            pa[2] = packh2(sc[2*kt + 1][0], sc[2*kt + 1][1]);
            pa[3] = packh2(sc[2*kt + 1][2], sc[2*kt + 1][3]);
            #pragma unroll
            for (int dp = 0; dp < 4; dp++) {
                uint32_t vbf[4];
                ldsm4t(vbf, vsm + kt * 16 * AROWB + dp * 32 + aOff);
                mma16816(o[2*dp],     pa, vbf[0], vbf[1]);
                mma16816(o[2*dp + 1], pa, vbf[2], vbf[3]);
            }
        }
        __syncthreads();
    }

    float invl0 = 1.0f / l0, invl1 = 1.0f / l1;
    size_t r0 = (size_t)bi * SEQ + i0 + wm + (lane >> 2);
    int colb = h * DHEAD + 2 * (lane & 3);
    #pragma unroll
    for (int nt = 0; nt < 8; nt++) {
        float y0 = o[nt][0] * invl0, y1 = o[nt][1] * invl0;
        float y2 = o[nt][2] * invl1, y3 = o[nt][3] * invl1;
        __half h0 = __float2half_rn(y0), h1 = __float2half_rn(y1);
        __half h2 = __float2half_rn(y2), h3 = __float2half_rn(y3);
        size_t p0 = r0 * DIMC + colb + nt * 8;
        size_t p1 = (r0 + 8) * DIMC + colb + nt * 8;
        *(__half2*)(ohi + p0) = __halves2half2(h0, h1);
        *(__half2*)(ohi + p1) = __halves2half2(h2, h3);
        *(__half2*)(olo + p0) = __halves2half2(
            __float2half_rn(y0 - __half2float(h0)), __float2half_rn(y1 - __half2float(h1)));
        *(__half2*)(olo + p1) = __halves2half2(
            __float2half_rn(y2 - __half2float(h2)), __float2half_rn(y3 - __half2float(h3)));
    }
}

// ---------------------------------------------------------------------------
extern "C" void kernel_launch(void* const* d_in, const int* in_sizes, int n_in,
                              void* d_out, int out_size) {
    const float* x     = (const float*)d_in[0];
    const float* ctx   = (const float*)d_in[1];
    const float* alibi = (const float*)d_in[2];
    const float* Wq    = (const float*)d_in[3];
    const float* Wk    = (const float*)d_in[4];
    const float* Wv    = (const float*)d_in[5];
    const float* Wo    = (const float*)d_in[6];
    const float* bo    = (const float*)d_in[7];
    const float* ln_w  = (const float*)d_in[8];
    const float* ln_b  = (const float*)d_in[9];
    float* out = (float*)d_out;

    __half *xhi, *chi, *ahi, *alo, *wb, *qh, *kh, *vh;
    cudaGetSymbolAddress((void**)&xhi, g_xhi);
    cudaGetSymbolAddress((void**)&chi, g_chi);
    cudaGetSymbolAddress((void**)&ahi, g_ahi);
    cudaGetSymbolAddress((void**)&alo, g_alo);
    cudaGetSymbolAddress((void**)&wb,  g_wb);
    cudaGetSymbolAddress((void**)&qh,  g_qh);
    cudaGetSymbolAddress((void**)&kh,  g_kh);
    cudaGetSymbolAddress((void**)&vh,  g_vh);

    size_t wsz = (size_t)DIMC * DIMC;
    __half *wq16 = wb;
    __half *wk16 = wb + wsz;
    __half *wv16 = wb + 2 * wsz;
    __half *wo16 = wb + 3 * wsz;

    ln_kernel<<<NROWS, 256>>>(x,   ln_w, ln_b, xhi);
    ln_kernel<<<NROWS, 256>>>(ctx, ln_w, ln_b, chi);

    int n4 = DIMC * DIMC / 4;
    dim3 gc(n4 / 256, 4);
    cvt_kernel<<<gc, 256>>>((const float4*)Wq, (const float4*)Wk,
                            (const float4*)Wv, (const float4*)Wo, wb, n4);

    cudaFuncSetAttribute(qkv_gemm, cudaFuncAttributeMaxDynamicSharedMemorySize, GSMEM1);
    cudaFuncSetAttribute(wo_gemm,  cudaFuncAttributeMaxDynamicSharedMemorySize, GSMEM2);

    dim3 gq(DIMC / 128, NROWS / 128, 3);
    qkv_gemm<<<gq, 256, GSMEM1>>>(xhi, chi, wq16, wk16, wv16, qh, kh, vh);

    cudaFuncSetAttribute(attn_kernel, cudaFuncAttributeMaxDynamicSharedMemorySize, ASMEM);
    dim3 ga(SEQ / 64, NB * NHEAD);
    attn_kernel<<<ga, 128, ASMEM>>>(qh, kh, vh, alibi, ahi, alo);

    dim3 gg(DIMC / 128, NROWS / 128);
    wo_gemm<<<gg, 256, GSMEM2>>>(ahi, alo, wo16, bo, out);
}

// round 13
// speedup vs baseline: 4.1987x; 1.0623x over previous
#include <cuda_runtime.h>
#include <cuda_fp16.h>
#include <math.h>
#include <stdint.h>

#define DIMC   1024
#define NHEAD  16
#define DHEAD  64
#define SEQ    2048
#define NB     2
#define NROWS  (NB * SEQ)       // 4096
#define ATT_SCALE 0.125f

// ---------------------------------------------------------------------------
// Scratch (device globals; no allocation allowed)
// ---------------------------------------------------------------------------
__device__ __half g_xhi[(size_t)NROWS * DIMC];
__device__ __half g_chi[(size_t)NROWS * DIMC];
__device__ __half g_ahi[(size_t)NROWS * DIMC];
__device__ __half g_alo[(size_t)NROWS * DIMC];
__device__ __half g_wb[4ul * DIMC * DIMC];   // wq, wk, wv, wo (fp16)
__device__ __half g_qh[(size_t)NROWS * DIMC];
__device__ __half g_kh[(size_t)NROWS * DIMC];
__device__ __half g_vh[(size_t)NROWS * DIMC];

// ---------------------------------------------------------------------------
// PTX helpers (sm_80 baseline only)
// ---------------------------------------------------------------------------
__device__ __forceinline__ uint32_t smem_u32(const void* p) {
    uint32_t a;
    asm("{ .reg .u64 t; cvta.to.shared.u64 t, %1; cvt.u32.u64 %0, t; }" : "=r"(a) : "l"(p));
    return a;
}
__device__ __forceinline__ void cp16(uint32_t dst, const void* src) {
    asm volatile("cp.async.cg.shared.global [%0], [%1], 16;" :: "r"(dst), "l"(src));
}
__device__ __forceinline__ void ldsm4(uint32_t* r, uint32_t addr) {
    asm volatile("ldmatrix.sync.aligned.m8n8.x4.shared.b16 {%0,%1,%2,%3}, [%4];"
        : "=r"(r[0]), "=r"(r[1]), "=r"(r[2]), "=r"(r[3]) : "r"(addr));
}
__device__ __forceinline__ void ldsm4t(uint32_t* r, uint32_t addr) {
    asm volatile("ldmatrix.sync.aligned.m8n8.x4.trans.shared.b16 {%0,%1,%2,%3}, [%4];"
        : "=r"(r[0]), "=r"(r[1]), "=r"(r[2]), "=r"(r[3]) : "r"(addr));
}
__device__ __forceinline__ void mma16816(float* c, const uint32_t* a,
                                         uint32_t b0, uint32_t b1) {
    asm volatile("mma.sync.aligned.m16n8k16.row.col.f32.f16.f16.f32 "
        "{%0,%1,%2,%3}, {%4,%5,%6,%7}, {%8,%9}, {%0,%1,%2,%3};"
        : "+f"(c[0]), "+f"(c[1]), "+f"(c[2]), "+f"(c[3])
        : "r"(a[0]), "r"(a[1]), "r"(a[2]), "r"(a[3]), "r"(b0), "r"(b1));
}
__device__ __forceinline__ uint32_t packh2(float a, float b) {
    __half2 h = __floats2half2_rn(a, b);
    return *(uint32_t*)&h;
}

// ---------------------------------------------------------------------------
// LayerNorm -> fp16 (merged: blockIdx.y selects x / ctx)
// ---------------------------------------------------------------------------
__global__ void __launch_bounds__(256) ln_kernel(const float* __restrict__ in0,
                                                 const float* __restrict__ in1,
                                                 const float* __restrict__ w,
                                                 const float* __restrict__ bvec,
                                                 __half* __restrict__ out0,
                                                 __half* __restrict__ out1) {
    const float* in = blockIdx.y ? in1 : in0;
    __half* hi      = blockIdx.y ? out1 : out0;
    int row = blockIdx.x;
    int t = threadIdx.x;
    const float4* rp = (const float4*)(in + (size_t)row * DIMC);
    float4 v = rp[t];
    float s  = v.x + v.y + v.z + v.w;
    float ss = v.x*v.x + v.y*v.y + v.z*v.z + v.w*v.w;

    __shared__ float s_sum[8], s_sq[8], s_stats[2];
    #pragma unroll
    for (int o = 16; o; o >>= 1) {
        s  += __shfl_xor_sync(0xffffffffu, s,  o);
        ss += __shfl_xor_sync(0xffffffffu, ss, o);
    }
    int lane = t & 31, wid = t >> 5;
    if (lane == 0) { s_sum[wid] = s; s_sq[wid] = ss; }
    __syncthreads();
    if (t == 0) {
        float a = 0.f, b2 = 0.f;
        #pragma unroll
        for (int i = 0; i < 8; i++) { a += s_sum[i]; b2 += s_sq[i]; }
        float mean = a * (1.0f / DIMC);
        float var  = b2 * (1.0f / DIMC) - mean * mean;
        s_stats[0] = mean;
        s_stats[1] = rsqrtf(var + 1e-5f);
    }
    __syncthreads();
    float mean = s_stats[0], inv = s_stats[1];
    float4 wv = ((const float4*)w)[t];
    float4 bv = ((const float4*)bvec)[t];
    __half h0 = __float2half_rn((v.x - mean) * inv * wv.x + bv.x);
    __half h1 = __float2half_rn((v.y - mean) * inv * wv.y + bv.y);
    __half h2 = __float2half_rn((v.z - mean) * inv * wv.z + bv.z);
    __half h3 = __float2half_rn((v.w - mean) * inv * wv.w + bv.w);
    size_t base = (size_t)row * DIMC + t * 4;
    *(__half2*)(hi + base)     = __halves2half2(h0, h1);
    *(__half2*)(hi + base + 2) = __halves2half2(h2, h3);
}

// Convert 4 float matrices to fp16 in one launch (y selects matrix)
__global__ void __launch_bounds__(256) cvt_kernel(const float4* __restrict__ w0,
                                                  const float4* __restrict__ w1,
                                                  const float4* __restrict__ w2,
                                                  const float4* __restrict__ w3,
                                                  __half* __restrict__ out, int n4) {
    int z = blockIdx.y;
    const float4* in = (z == 0) ? w0 : (z == 1) ? w1 : (z == 2) ? w2 : w3;
    int i = blockIdx.x * blockDim.x + threadIdx.x;
    if (i >= n4) return;
    float4 v = in[i];
    size_t base = (size_t)z * (DIMC * DIMC) + (size_t)i * 4;
    *(__half2*)(out + base)     = __floats2half2_rn(v.x, v.y);
    *(__half2*)(out + base + 2) = __floats2half2_rn(v.z, v.w);
}

// ---------------------------------------------------------------------------
// mma.sync GEMM core, 3-stage cp.async pipeline, ONE barrier per chunk.
// PASSES=1: Ah*Bh (stage: A, B).  PASSES=2: Ah*Bh + Al*Bh (stage: A, Alo, B).
// OUT=0: fp32 + bias; OUT=1: fp16.
// ---------------------------------------------------------------------------
#define BK        32
#define NCHUNK    (DIMC / BK)            // 32
#define ROWB      80
#define MATB      (128 * ROWB)
#define NSTAGE    3
#define GSMEM1    (NSTAGE * 2 * MATB)    // 61440 (1-pass)
#define GSMEM2    (NSTAGE * 3 * MATB)    // 92160 (2-pass)

template<int PASSES, int OUT>
__device__ __forceinline__ void gemm_core(
    const __half* __restrict__ Ahi, const __half* __restrict__ Alo,
    const __half* __restrict__ Bhi,
    const float* __restrict__ bias, void* __restrict__ Cv,
    int mBase, int nBase)
{
    extern __shared__ char smem[];
    uint32_t sb = smem_u32(smem);
    const int NA = (PASSES >= 2) ? 2 : 1;          // A matrices per stage
    const uint32_t BOFF = NA * MATB;               // B offset within stage
    const uint32_t STG = (NA + 1) * MATB;

    int tid = threadIdx.x, wid = tid >> 5, lane = tid & 31;

    int lrow = tid & 127;
    int chb  = tid >> 7;
    const char* pAhi = (const char*)Ahi + (size_t)(mBase + lrow) * (DIMC * 2);
    const char* pAlo = (PASSES >= 2) ? (const char*)Alo + (size_t)(mBase + lrow) * (DIMC * 2)
                                     : nullptr;
    const char* pBhi = (const char*)Bhi + (size_t)(nBase + lrow) * (DIMC * 2);

    auto load_chunk = [&](int c, int s) {
        uint32_t stb = sb + s * STG + lrow * ROWB;
        size_t ko = (size_t)c * (BK * 2);
        #pragma unroll
        for (int i = 0; i < 2; i++) {
            int ch = chb + 2 * i;
            uint32_t d = stb + ch * 16;
            size_t so = ko + ch * 16;
            cp16(d, pAhi + so);
            if (PASSES >= 2) cp16(d + MATB, pAlo + so);
            cp16(d + BOFF, pBhi + so);
        }
    };

    float acc[4][4][4];
    #pragma unroll
    for (int a = 0; a < 4; a++)
        #pragma unroll
        for (int b = 0; b < 4; b++)
            #pragma unroll
            for (int d = 0; d < 4; d++) acc[a][b][d] = 0.f;

    int wm = (wid >> 2) * 64;
    int wn = (wid & 3) * 32;

    uint32_t aLaneOff = (uint32_t)((lane & 15) * ROWB + (lane >> 4) * 16);
    uint32_t bLaneOff = (uint32_t)((((lane & 7) + ((lane >> 4) << 3)) * ROWB)
                                   + (((lane >> 3) & 1) * 16));

    // prologue: stages 0, 1 in flight
    load_chunk(0, 0);
    asm volatile("cp.async.commit_group;");
    load_chunk(1, 1);
    asm volatile("cp.async.commit_group;");

    for (int c = 0; c < NCHUNK; c++) {
        int s = c % NSTAGE;
        asm volatile("cp.async.wait_group 1;" ::: "memory");   // chunk c resident
        __syncthreads();   // all warps see stage s; stage (c-1)%3 reads done

        if (c + 2 < NCHUNK) {
            load_chunk(c + 2, (c + 2) % NSTAGE);
            asm volatile("cp.async.commit_group;");
        } else {
            // keep outstanding-group accounting uniform for wait_group 1
            asm volatile("cp.async.commit_group;");
        }

        uint32_t stb = sb + s * STG;
        #pragma unroll
        for (int ks = 0; ks < 2; ks++) {
            uint32_t kbB = ks * 32;
            uint32_t bh[2][4];
            #pragma unroll
            for (int p = 0; p < 2; p++)
                ldsm4(bh[p], stb + BOFF + (wn + p * 16) * ROWB + kbB + bLaneOff);
            #pragma unroll
            for (int mt = 0; mt < 4; mt++) {
                uint32_t aa = stb + (wm + mt * 16) * ROWB + kbB + aLaneOff;
                uint32_t ah[4], al[4];
                ldsm4(ah, aa);
                if (PASSES >= 2) ldsm4(al, aa + MATB);
                #pragma unroll
                for (int p = 0; p < 2; p++) {
                    mma16816(acc[mt][2*p],     ah, bh[p][0], bh[p][1]);
                    mma16816(acc[mt][2*p + 1], ah, bh[p][2], bh[p][3]);
                    if (PASSES >= 2) {
                        mma16816(acc[mt][2*p],     al, bh[p][0], bh[p][1]);
                        mma16816(acc[mt][2*p + 1], al, bh[p][2], bh[p][3]);
                    }
                }
            }
        }
    }

    #pragma unroll
    for (int mt = 0; mt < 4; mt++) {
        #pragma unroll
        for (int nt = 0; nt < 4; nt++) {
            int row0 = mBase + wm + mt * 16 + (lane >> 2);
            int col  = nBase + wn + nt * 8 + (lane & 3) * 2;
            if (OUT == 0) {
                float* C = (float*)Cv;
                float2 v0 = make_float2(acc[mt][nt][0], acc[mt][nt][1]);
                float2 v1 = make_float2(acc[mt][nt][2], acc[mt][nt][3]);
                float2 bb = *(const float2*)(bias + col);
                v0.x += bb.x; v0.y += bb.y;
                v1.x += bb.x; v1.y += bb.y;
                *(float2*)(C + (size_t)row0 * DIMC + col)       = v0;
                *(float2*)(C + (size_t)(row0 + 8) * DIMC + col) = v1;
            } else {
                __half* C = (__half*)Cv;
                *(__half2*)(C + (size_t)row0 * DIMC + col) =
                    __floats2half2_rn(acc[mt][nt][0], acc[mt][nt][1]);
                *(__half2*)(C + (size_t)(row0 + 8) * DIMC + col) =
                    __floats2half2_rn(acc[mt][nt][2], acc[mt][nt][3]);
            }
        }
    }
}

// Merged QKV: blockIdx.z selects operands; 1-pass fp16.
__global__ void __launch_bounds__(256, 2) qkv_gemm(
    const __half* __restrict__ xhi, const __half* __restrict__ chi,
    const __half* __restrict__ wq, const __half* __restrict__ wk,
    const __half* __restrict__ wv,
    __half* __restrict__ qh, __half* __restrict__ kh, __half* __restrict__ vh)
{
    int z = blockIdx.z;
    const __half* A = (z == 0) ? xhi : chi;
    const __half* B = (z == 0) ? wq : (z == 1) ? wk : wv;
    __half* C       = (z == 0) ? qh : (z == 1) ? kh : vh;
    gemm_core<1, 1>(A, nullptr, B, nullptr, C, blockIdx.y * 128, blockIdx.x * 128);
}

// Output projection: 2-pass (attention-output hi/lo), fp32 + bias.
__global__ void __launch_bounds__(256, 2) wo_gemm(
    const __half* __restrict__ Ahi, const __half* __restrict__ Alo,
    const __half* __restrict__ Bhi,
    const float* __restrict__ bias, float* __restrict__ C)
{
    gemm_core<2, 0>(Ahi, Alo, Bhi, bias, C, blockIdx.y * 128, blockIdx.x * 128);
}

// ---------------------------------------------------------------------------
// Flash attention, mma.sync fp16 (validated R8/R9/R11, incl. alibi-L2 remap).
// ---------------------------------------------------------------------------
#define AROWB 144
#define QSM_BYTES (64 * AROWB)           // 9216
#define KVSTAGE   (2 * QSM_BYTES)
#define ASMEM     (QSM_BYTES + 2 * KVSTAGE)   // 46080

__global__ void __launch_bounds__(128) attn_kernel(const __half* __restrict__ q,
                                                   const __half* __restrict__ k,
                                                   const __half* __restrict__ v,
                                                   const float* __restrict__ alibi,
                                                   __half* __restrict__ ohi,
                                                   __half* __restrict__ olo) {
    extern __shared__ char smx[];
    uint32_t sq = smem_u32(smx);

    int bh = blockIdx.y;
    int h  = bh >> 1;
    int bi = bh & 1;
    int i0 = blockIdx.x * 64;
    int tid = threadIdx.x, wid = tid >> 5, lane = tid & 31;
    int wm = wid * 16;

    const char* qb = (const char*)(q + ((size_t)bi * SEQ + i0) * DIMC + h * DHEAD);
    const char* kb = (const char*)(k + ((size_t)bi * SEQ) * DIMC + h * DHEAD);
    const char* vb = (const char*)(v + ((size_t)bi * SEQ) * DIMC + h * DHEAD);

    int lr = tid >> 1;
    int lc = (tid & 1) * 64;
    uint32_t dOff = (uint32_t)(lr * AROWB + lc);
    size_t gOff = (size_t)lr * (DIMC * 2) + lc;

    #pragma unroll
    for (int i = 0; i < 4; i++) cp16(sq + dOff + i * 16, qb + gOff + i * 16);

    auto load_kv = [&](int j0, int s) {
        uint32_t ks_ = sq + QSM_BYTES + s * KVSTAGE;
        uint32_t vs_ = ks_ + QSM_BYTES;
        size_t g = gOff + (size_t)j0 * (DIMC * 2);
        #pragma unroll
        for (int i = 0; i < 4; i++) {
            cp16(ks_ + dOff + i * 16, kb + g + i * 16);
            cp16(vs_ + dOff + i * 16, vb + g + i * 16);
        }
    };

    load_kv(0, 0);
    asm volatile("cp.async.commit_group;");

    uint32_t aOff = (uint32_t)((lane & 15) * AROWB + (lane >> 4) * 16);
    uint32_t bOff = (uint32_t)((((lane & 7) + ((lane >> 4) << 3)) * AROWB)
                               + (((lane >> 3) & 1) * 16));

    float m0 = -INFINITY, m1 = -INFINITY, l0 = 0.f, l1 = 0.f;
    float o[8][4];
    #pragma unroll
    for (int nt = 0; nt < 8; nt++)
        #pragma unroll
        for (int c = 0; c < 4; c++) o[nt][c] = 0.f;

    const float* ab = alibi + ((size_t)h * SEQ + i0 + wm + (lane >> 2)) * SEQ + 2 * (lane & 3);

    for (int jt = 0; jt < SEQ / 64; jt++) {
        int s = jt & 1;
        if (jt + 1 < SEQ / 64) {
            load_kv((jt + 1) * 64, s ^ 1);
            asm volatile("cp.async.commit_group;");
            asm volatile("cp.async.wait_group 1;" ::: "memory");
        } else {
            asm volatile("cp.async.wait_group 0;" ::: "memory");
        }
        __syncthreads();

        uint32_t ksm = sq + QSM_BYTES + s * KVSTAGE;
        uint32_t vsm = ksm + QSM_BYTES;

        float sc[8][4];
        #pragma unroll
        for (int nt = 0; nt < 8; nt++)
            #pragma unroll
            for (int c = 0; c < 4; c++) sc[nt][c] = 0.f;
        #pragma unroll
        for (int kt = 0; kt < 4; kt++) {
            uint32_t a[4];
            ldsm4(a, sq + wm * AROWB + kt * 32 + aOff);
            #pragma unroll
            for (int p = 0; p < 4; p++) {
                uint32_t b[4];
                ldsm4(b, ksm + p * 16 * AROWB + kt * 32 + bOff);
                mma16816(sc[2*p],     a, b[0], b[1]);
                mma16816(sc[2*p + 1], a, b[2], b[3]);
            }
        }

        int j0 = jt * 64;
        #pragma unroll
        for (int nt = 0; nt < 8; nt++) {
            float2 al0 = *(const float2*)(ab + j0 + nt * 8);
            float2 al1 = *(const float2*)(ab + 8 * SEQ + j0 + nt * 8);
            sc[nt][0] = fmaf(sc[nt][0], ATT_SCALE, al0.x);
            sc[nt][1] = fmaf(sc[nt][1], ATT_SCALE, al0.y);
            sc[nt][2] = fmaf(sc[nt][2], ATT_SCALE, al1.x);
            sc[nt][3] = fmaf(sc[nt][3], ATT_SCALE, al1.y);
        }

        float mx0 = -INFINITY, mx1 = -INFINITY;
        #pragma unroll
        for (int nt = 0; nt < 8; nt++) {
            mx0 = fmaxf(mx0, fmaxf(sc[nt][0], sc[nt][1]));
            mx1 = fmaxf(mx1, fmaxf(sc[nt][2], sc[nt][3]));
        }
        mx0 = fmaxf(mx0, __shfl_xor_sync(0xffffffffu, mx0, 1));
        mx0 = fmaxf(mx0, __shfl_xor_sync(0xffffffffu, mx0, 2));
        mx1 = fmaxf(mx1, __shfl_xor_sync(0xffffffffu, mx1, 1));
        mx1 = fmaxf(mx1, __shfl_xor_sync(0xffffffffu, mx1, 2));

        float mn0 = fmaxf(m0, mx0), mn1 = fmaxf(m1, mx1);
        float alpha0 = __expf(m0 - mn0), alpha1 = __expf(m1 - mn1);
        m0 = mn0; m1 = mn1;

        float rs0 = 0.f, rs1 = 0.f;
        #pragma unroll
        for (int nt = 0; nt < 8; nt++) {
            sc[nt][0] = __expf(sc[nt][0] - mn0); rs0 += sc[nt][0];
            sc[nt][1] = __expf(sc[nt][1] - mn0); rs0 += sc[nt][1];
            sc[nt][2] = __expf(sc[nt][2] - mn1); rs1 += sc[nt][2];
            sc[nt][3] = __expf(sc[nt][3] - mn1); rs1 += sc[nt][3];
        }
        rs0 += __shfl_xor_sync(0xffffffffu, rs0, 1);
        rs0 += __shfl_xor_sync(0xffffffffu, rs0, 2);
        rs1 += __shfl_xor_sync(0xffffffffu, rs1, 1);
        rs1 += __shfl_xor_sync(0xffffffffu, rs1, 2);
        l0 = l0 * alpha0 + rs0;
        l1 = l1 * alpha1 + rs1;

        #pragma unroll
        for (int nt = 0; nt < 8; nt++) {
            o[nt][0] *= alpha0; o[nt][1] *= alpha0;
            o[nt][2] *= alpha1; o[nt][3] *= alpha1;
        }

        #pragma unroll
        for (int kt = 0; kt < 4; kt++) {
            uint32_t pa[4];
            pa[0] = packh2(sc[2*kt][0],     sc[2*kt][1]);
            pa[1] = packh2(sc[2*kt][2],     sc[2*kt][3]);
            pa[2] = packh2(sc[2*kt + 1][0], sc[2*kt + 1][1]);
            pa[3] = packh2(sc[2*kt + 1][2], sc[2*kt + 1][3]);
            #pragma unroll
            for (int dp = 0; dp < 4; dp++) {
                uint32_t vbf[4];
                ldsm4t(vbf, vsm + kt * 16 * AROWB + dp * 32 + aOff);
                mma16816(o[2*dp],     pa, vbf[0], vbf[1]);
                mma16816(o[2*dp + 1], pa, vbf[2], vbf[3]);
            }
        }
        __syncthreads();
    }

    float invl0 = 1.0f / l0, invl1 = 1.0f / l1;
    size_t r0 = (size_t)bi * SEQ + i0 + wm + (lane >> 2);
    int colb = h * DHEAD + 2 * (lane & 3);
    #pragma unroll
    for (int nt = 0; nt < 8; nt++) {
        float y0 = o[nt][0] * invl0, y1 = o[nt][1] * invl0;
        float y2 = o[nt][2] * invl1, y3 = o[nt][3] * invl1;
        __half h0 = __float2half_rn(y0), h1 = __float2half_rn(y1);
        __half h2 = __float2half_rn(y2), h3 = __float2half_rn(y3);
        size_t p0 = r0 * DIMC + colb + nt * 8;
        size_t p1 = (r0 + 8) * DIMC + colb + nt * 8;
        *(__half2*)(ohi + p0) = __halves2half2(h0, h1);
        *(__half2*)(ohi + p1) = __halves2half2(h2, h3);
        *(__half2*)(olo + p0) = __halves2half2(
            __float2half_rn(y0 - __half2float(h0)), __float2half_rn(y1 - __half2float(h1)));
        *(__half2*)(olo + p1) = __halves2half2(
            __float2half_rn(y2 - __half2float(h2)), __float2half_rn(y3 - __half2float(h3)));
    }
}

// ---------------------------------------------------------------------------
extern "C" void kernel_launch(void* const* d_in, const int* in_sizes, int n_in,
                              void* d_out, int out_size) {
    const float* x     = (const float*)d_in[0];
    const float* ctx   = (const float*)d_in[1];
    const float* alibi = (const float*)d_in[2];
    const float* Wq    = (const float*)d_in[3];
    const float* Wk    = (const float*)d_in[4];
    const float* Wv    = (const float*)d_in[5];
    const float* Wo    = (const float*)d_in[6];
    const float* bo    = (const float*)d_in[7];
    const float* ln_w  = (const float*)d_in[8];
    const float* ln_b  = (const float*)d_in[9];
    float* out = (float*)d_out;

    __half *xhi, *chi, *ahi, *alo, *wb, *qh, *kh, *vh;
    cudaGetSymbolAddress((void**)&xhi, g_xhi);
    cudaGetSymbolAddress((void**)&chi, g_chi);
    cudaGetSymbolAddress((void**)&ahi, g_ahi);
    cudaGetSymbolAddress((void**)&alo, g_alo);
    cudaGetSymbolAddress((void**)&wb,  g_wb);
    cudaGetSymbolAddress((void**)&qh,  g_qh);
    cudaGetSymbolAddress((void**)&kh,  g_kh);
    cudaGetSymbolAddress((void**)&vh,  g_vh);

    size_t wsz = (size_t)DIMC * DIMC;
    __half *wq16 = wb;
    __half *wk16 = wb + wsz;
    __half *wv16 = wb + 2 * wsz;
    __half *wo16 = wb + 3 * wsz;

    dim3 gl(NROWS, 2);
    ln_kernel<<<gl, 256>>>(x, ctx, ln_w, ln_b, xhi, chi);

    int n4 = DIMC * DIMC / 4;
    dim3 gc(n4 / 256, 4);
    cvt_kernel<<<gc, 256>>>((const float4*)Wq, (const float4*)Wk,
                            (const float4*)Wv, (const float4*)Wo, wb, n4);

    cudaFuncSetAttribute(qkv_gemm, cudaFuncAttributeMaxDynamicSharedMemorySize, GSMEM1);
    cudaFuncSetAttribute(wo_gemm,  cudaFuncAttributeMaxDynamicSharedMemorySize, GSMEM2);

    dim3 gq(DIMC / 128, NROWS / 128, 3);
    qkv_gemm<<<gq, 256, GSMEM1>>>(xhi, chi, wq16, wk16, wv16, qh, kh, vh);

    cudaFuncSetAttribute(attn_kernel, cudaFuncAttributeMaxDynamicSharedMemorySize, ASMEM);
    dim3 ga(SEQ / 64, NB * NHEAD);
    attn_kernel<<<ga, 128, ASMEM>>>(qh, kh, vh, alibi, ahi, alo);

    dim3 gg(DIMC / 128, NROWS / 128);
    wo_gemm<<<gg, 256, GSMEM2>>>(ahi, alo, wo16, bo, out);
}

// round 14
// speedup vs baseline: 4.5645x; 1.0871x over previous
#include <cuda_runtime.h>
#include <cuda_fp16.h>
#include <math.h>
#include <stdint.h>

#define DIMC   1024
#define NHEAD  16
#define DHEAD  64
#define SEQ    2048
#define NB     2
#define NROWS  (NB * SEQ)       // 4096
#define ATT_SCALE 0.125f

// ---------------------------------------------------------------------------
// Scratch (device globals; no allocation allowed)
// ---------------------------------------------------------------------------
__device__ __half g_xhi[(size_t)NROWS * DIMC];
__device__ __half g_chi[(size_t)NROWS * DIMC];
__device__ __half g_ahi[(size_t)NROWS * DIMC];
__device__ __half g_alo[(size_t)NROWS * DIMC];
__device__ __half g_wb[4ul * DIMC * DIMC];   // wq, wk, wv, wo (fp16)
__device__ __half g_qh[(size_t)NROWS * DIMC];
__device__ __half g_kh[(size_t)NROWS * DIMC];
__device__ __half g_vh[(size_t)NROWS * DIMC];

// ---------------------------------------------------------------------------
// PTX helpers (sm_80 baseline only)
// ---------------------------------------------------------------------------
__device__ __forceinline__ uint32_t smem_u32(const void* p) {
    uint32_t a;
    asm("{ .reg .u64 t; cvta.to.shared.u64 t, %1; cvt.u32.u64 %0, t; }" : "=r"(a) : "l"(p));
    return a;
}
__device__ __forceinline__ void cp16(uint32_t dst, const void* src) {
    asm volatile("cp.async.cg.shared.global [%0], [%1], 16;" :: "r"(dst), "l"(src));
}
__device__ __forceinline__ void ldsm4(uint32_t* r, uint32_t addr) {
    asm volatile("ldmatrix.sync.aligned.m8n8.x4.shared.b16 {%0,%1,%2,%3}, [%4];"
        : "=r"(r[0]), "=r"(r[1]), "=r"(r[2]), "=r"(r[3]) : "r"(addr));
}
__device__ __forceinline__ void ldsm4t(uint32_t* r, uint32_t addr) {
    asm volatile("ldmatrix.sync.aligned.m8n8.x4.trans.shared.b16 {%0,%1,%2,%3}, [%4];"
        : "=r"(r[0]), "=r"(r[1]), "=r"(r[2]), "=r"(r[3]) : "r"(addr));
}
__device__ __forceinline__ void mma16816(float* c, const uint32_t* a,
                                         uint32_t b0, uint32_t b1) {
    asm volatile("mma.sync.aligned.m16n8k16.row.col.f32.f16.f16.f32 "
        "{%0,%1,%2,%3}, {%4,%5,%6,%7}, {%8,%9}, {%0,%1,%2,%3};"
        : "+f"(c[0]), "+f"(c[1]), "+f"(c[2]), "+f"(c[3])
        : "r"(a[0]), "r"(a[1]), "r"(a[2]), "r"(a[3]), "r"(b0), "r"(b1));
}
__device__ __forceinline__ uint32_t packh2(float a, float b) {
    __half2 h = __floats2half2_rn(a, b);
    return *(uint32_t*)&h;
}

// ---------------------------------------------------------------------------
// LayerNorm -> fp16 (merged: blockIdx.y selects x / ctx)
// ---------------------------------------------------------------------------
__global__ void __launch_bounds__(256) ln_kernel(const float* __restrict__ in0,
                                                 const float* __restrict__ in1,
                                                 const float* __restrict__ w,
                                                 const float* __restrict__ bvec,
                                                 __half* __restrict__ out0,
                                                 __half* __restrict__ out1) {
    const float* in = blockIdx.y ? in1 : in0;
    __half* hi      = blockIdx.y ? out1 : out0;
    int row = blockIdx.x;
    int t = threadIdx.x;
    const float4* rp = (const float4*)(in + (size_t)row * DIMC);
    float4 v = rp[t];
    float s  = v.x + v.y + v.z + v.w;
    float ss = v.x*v.x + v.y*v.y + v.z*v.z + v.w*v.w;

    __shared__ float s_sum[8], s_sq[8], s_stats[2];
    #pragma unroll
    for (int o = 16; o; o >>= 1) {
        s  += __shfl_xor_sync(0xffffffffu, s,  o);
        ss += __shfl_xor_sync(0xffffffffu, ss, o);
    }
    int lane = t & 31, wid = t >> 5;
    if (lane == 0) { s_sum[wid] = s; s_sq[wid] = ss; }
    __syncthreads();
    if (t == 0) {
        float a = 0.f, b2 = 0.f;
        #pragma unroll
        for (int i = 0; i < 8; i++) { a += s_sum[i]; b2 += s_sq[i]; }
        float mean = a * (1.0f / DIMC);
        float var  = b2 * (1.0f / DIMC) - mean * mean;
        s_stats[0] = mean;
        s_stats[1] = rsqrtf(var + 1e-5f);
    }
    __syncthreads();
    float mean = s_stats[0], inv = s_stats[1];
    float4 wv = ((const float4*)w)[t];
    float4 bv = ((const float4*)bvec)[t];
    __half h0 = __float2half_rn((v.x - mean) * inv * wv.x + bv.x);
    __half h1 = __float2half_rn((v.y - mean) * inv * wv.y + bv.y);
    __half h2 = __float2half_rn((v.z - mean) * inv * wv.z + bv.z);
    __half h3 = __float2half_rn((v.w - mean) * inv * wv.w + bv.w);
    size_t base = (size_t)row * DIMC + t * 4;
    *(__half2*)(hi + base)     = __halves2half2(h0, h1);
    *(__half2*)(hi + base + 2) = __halves2half2(h2, h3);
}

// Convert 4 float matrices to fp16 in one launch (y selects matrix)
__global__ void __launch_bounds__(256) cvt_kernel(const float4* __restrict__ w0,
                                                  const float4* __restrict__ w1,
                                                  const float4* __restrict__ w2,
                                                  const float4* __restrict__ w3,
                                                  __half* __restrict__ out, int n4) {
    int z = blockIdx.y;
    const float4* in = (z == 0) ? w0 : (z == 1) ? w1 : (z == 2) ? w2 : w3;
    int i = blockIdx.x * blockDim.x + threadIdx.x;
    if (i >= n4) return;
    float4 v = in[i];
    size_t base = (size_t)z * (DIMC * DIMC) + (size_t)i * 4;
    *(__half2*)(out + base)     = __floats2half2_rn(v.x, v.y);
    *(__half2*)(out + base + 2) = __floats2half2_rn(v.z, v.w);
}

// ---------------------------------------------------------------------------
// mma.sync GEMM core, 3-stage cp.async pipeline, ONE barrier per chunk.
// PASSES=1: Ah*Bh (stage: A, B).  PASSES=2: Ah*Bh + Al*Bh (stage: A, Alo, B).
// OUT=0: fp32 + bias; OUT=1: fp16 (scaled by cscale).
// ---------------------------------------------------------------------------
#define BK        32
#define NCHUNK    (DIMC / BK)            // 32
#define ROWB      80
#define MATB      (128 * ROWB)
#define NSTAGE    3
#define GSMEM1    (NSTAGE * 2 * MATB)    // 61440 (1-pass)
#define GSMEM2    (NSTAGE * 3 * MATB)    // 92160 (2-pass)

template<int PASSES, int OUT>
__device__ __forceinline__ void gemm_core(
    const __half* __restrict__ Ahi, const __half* __restrict__ Alo,
    const __half* __restrict__ Bhi,
    const float* __restrict__ bias, void* __restrict__ Cv,
    int mBase, int nBase, float cscale)
{
    extern __shared__ char smem[];
    uint32_t sb = smem_u32(smem);
    const int NA = (PASSES >= 2) ? 2 : 1;          // A matrices per stage
    const uint32_t BOFF = NA * MATB;               // B offset within stage
    const uint32_t STG = (NA + 1) * MATB;

    int tid = threadIdx.x, wid = tid >> 5, lane = tid & 31;

    int lrow = tid & 127;
    int chb  = tid >> 7;
    const char* pAhi = (const char*)Ahi + (size_t)(mBase + lrow) * (DIMC * 2);
    const char* pAlo = (PASSES >= 2) ? (const char*)Alo + (size_t)(mBase + lrow) * (DIMC * 2)
                                     : nullptr;
    const char* pBhi = (const char*)Bhi + (size_t)(nBase + lrow) * (DIMC * 2);

    auto load_chunk = [&](int c, int s) {
        uint32_t stb = sb + s * STG + lrow * ROWB;
        size_t ko = (size_t)c * (BK * 2);
        #pragma unroll
        for (int i = 0; i < 2; i++) {
            int ch = chb + 2 * i;
            uint32_t d = stb + ch * 16;
            size_t so = ko + ch * 16;
            cp16(d, pAhi + so);
            if (PASSES >= 2) cp16(d + MATB, pAlo + so);
            cp16(d + BOFF, pBhi + so);
        }
    };

    float acc[4][4][4];
    #pragma unroll
    for (int a = 0; a < 4; a++)
        #pragma unroll
        for (int b = 0; b < 4; b++)
            #pragma unroll
            for (int d = 0; d < 4; d++) acc[a][b][d] = 0.f;

    int wm = (wid >> 2) * 64;
    int wn = (wid & 3) * 32;

    uint32_t aLaneOff = (uint32_t)((lane & 15) * ROWB + (lane >> 4) * 16);
    uint32_t bLaneOff = (uint32_t)((((lane & 7) + ((lane >> 4) << 3)) * ROWB)
                                   + (((lane >> 3) & 1) * 16));

    // prologue: stages 0, 1 in flight
    load_chunk(0, 0);
    asm volatile("cp.async.commit_group;");
    load_chunk(1, 1);
    asm volatile("cp.async.commit_group;");

    for (int c = 0; c < NCHUNK; c++) {
        int s = c % NSTAGE;
        asm volatile("cp.async.wait_group 1;" ::: "memory");   // chunk c resident
        __syncthreads();   // all warps see stage s; stage (c-1)%3 reads done

        if (c + 2 < NCHUNK) {
            load_chunk(c + 2, (c + 2) % NSTAGE);
            asm volatile("cp.async.commit_group;");
        } else {
            asm volatile("cp.async.commit_group;");
        }

        uint32_t stb = sb + s * STG;
        #pragma unroll
        for (int ks = 0; ks < 2; ks++) {
            uint32_t kbB = ks * 32;
            uint32_t bh[2][4];
            #pragma unroll
            for (int p = 0; p < 2; p++)
                ldsm4(bh[p], stb + BOFF + (wn + p * 16) * ROWB + kbB + bLaneOff);
            #pragma unroll
            for (int mt = 0; mt < 4; mt++) {
                uint32_t aa = stb + (wm + mt * 16) * ROWB + kbB + aLaneOff;
                uint32_t ah[4], al[4];
                ldsm4(ah, aa);
                if (PASSES >= 2) ldsm4(al, aa + MATB);
                #pragma unroll
                for (int p = 0; p < 2; p++) {
                    mma16816(acc[mt][2*p],     ah, bh[p][0], bh[p][1]);
                    mma16816(acc[mt][2*p + 1], ah, bh[p][2], bh[p][3]);
                    if (PASSES >= 2) {
                        mma16816(acc[mt][2*p],     al, bh[p][0], bh[p][1]);
                        mma16816(acc[mt][2*p + 1], al, bh[p][2], bh[p][3]);
                    }
                }
            }
        }
    }

    #pragma unroll
    for (int mt = 0; mt < 4; mt++) {
        #pragma unroll
        for (int nt = 0; nt < 4; nt++) {
            int row0 = mBase + wm + mt * 16 + (lane >> 2);
            int col  = nBase + wn + nt * 8 + (lane & 3) * 2;
            if (OUT == 0) {
                float* C = (float*)Cv;
                float2 v0 = make_float2(acc[mt][nt][0], acc[mt][nt][1]);
                float2 v1 = make_float2(acc[mt][nt][2], acc[mt][nt][3]);
                float2 bb = *(const float2*)(bias + col);
                v0.x += bb.x; v0.y += bb.y;
                v1.x += bb.x; v1.y += bb.y;
                *(float2*)(C + (size_t)row0 * DIMC + col)       = v0;
                *(float2*)(C + (size_t)(row0 + 8) * DIMC + col) = v1;
            } else {
                __half* C = (__half*)Cv;
                *(__half2*)(C + (size_t)row0 * DIMC + col) =
                    __floats2half2_rn(acc[mt][nt][0] * cscale, acc[mt][nt][1] * cscale);
                *(__half2*)(C + (size_t)(row0 + 8) * DIMC + col) =
                    __floats2half2_rn(acc[mt][nt][2] * cscale, acc[mt][nt][3] * cscale);
            }
        }
    }
}

// Merged QKV: blockIdx.z selects operands; 1-pass fp16. Q is pre-scaled by
// ATT_SCALE (2^-3, exact) so attention skips the scale step.
__global__ void __launch_bounds__(256, 2) qkv_gemm(
    const __half* __restrict__ xhi, const __half* __restrict__ chi,
    const __half* __restrict__ wq, const __half* __restrict__ wk,
    const __half* __restrict__ wv,
    __half* __restrict__ qh, __half* __restrict__ kh, __half* __restrict__ vh)
{
    int z = blockIdx.z;
    const __half* A = (z == 0) ? xhi : chi;
    const __half* B = (z == 0) ? wq : (z == 1) ? wk : wv;
    __half* C       = (z == 0) ? qh : (z == 1) ? kh : vh;
    float cs        = (z == 0) ? ATT_SCALE : 1.0f;
    gemm_core<1, 1>(A, nullptr, B, nullptr, C, blockIdx.y * 128, blockIdx.x * 128, cs);
}

// Output projection: 2-pass (attention-output hi/lo), fp32 + bias.
__global__ void __launch_bounds__(256, 2) wo_gemm(
    const __half* __restrict__ Ahi, const __half* __restrict__ Alo,
    const __half* __restrict__ Bhi,
    const float* __restrict__ bias, float* __restrict__ C)
{
    gemm_core<2, 0>(Ahi, Alo, Bhi, bias, C, blockIdx.y * 128, blockIdx.x * 128, 1.0f);
}

// ---------------------------------------------------------------------------
// Flash attention, mma.sync fp16. BM=128 (8 warps), BN=64.
// Alibi is preloaded into the S accumulator fragments before the KV wait and
// QK MMAs (Q is pre-scaled, so S = QK + alibi directly).
// ---------------------------------------------------------------------------
#define AROWB 144
#define QSM_B  (128 * AROWB)             // 18432 (Q tile, 128 rows)
#define KVTILE (64 * AROWB)              // 9216 (one K or V tile)
#define KVSTG  (2 * KVTILE)              // 18432 per stage (K + V)
#define ASMEM  (QSM_B + 2 * KVSTG)       // 55296

__global__ void __launch_bounds__(256, 2) attn_kernel(const __half* __restrict__ q,
                                                      const __half* __restrict__ k,
                                                      const __half* __restrict__ v,
                                                      const float* __restrict__ alibi,
                                                      __half* __restrict__ ohi,
                                                      __half* __restrict__ olo) {
    extern __shared__ char smx[];
    uint32_t sq = smem_u32(smx);

    int bh = blockIdx.y;
    int h  = bh >> 1;
    int bi = bh & 1;
    int i0 = blockIdx.x * 128;
    int tid = threadIdx.x, wid = tid >> 5, lane = tid & 31;
    int wm = wid * 16;

    const char* qb = (const char*)(q + ((size_t)bi * SEQ + i0) * DIMC + h * DHEAD);
    const char* kb = (const char*)(k + ((size_t)bi * SEQ) * DIMC + h * DHEAD);
    const char* vb = (const char*)(v + ((size_t)bi * SEQ) * DIMC + h * DHEAD);

    // Q loader: 256 threads cover 128 rows x 128B (2 threads/row, 4x16B each)
    {
        int lr = tid >> 1;
        int lc = (tid & 1) * 64;
        uint32_t d = sq + (uint32_t)(lr * AROWB + lc);
        const char* g = qb + (size_t)lr * (DIMC * 2) + lc;
        #pragma unroll
        for (int i = 0; i < 4; i++) cp16(d + i * 16, g + i * 16);
    }

    // KV loader geometry: 256 threads cover 64 rows x 128B (4 threads/row, 2x16B)
    int lrK = tid >> 2;
    int lcK = (tid & 3) * 32;
    uint32_t dKV = (uint32_t)(lrK * AROWB + lcK);
    size_t gKV = (size_t)lrK * (DIMC * 2) + lcK;

    auto load_kv = [&](int j0, int s) {
        uint32_t ks_ = sq + QSM_B + s * KVSTG;
        uint32_t vs_ = ks_ + KVTILE;
        size_t g = gKV + (size_t)j0 * (DIMC * 2);
        #pragma unroll
        for (int i = 0; i < 2; i++) {
            cp16(ks_ + dKV + i * 16, kb + g + i * 16);
            cp16(vs_ + dKV + i * 16, vb + g + i * 16);
        }
    };

    load_kv(0, 0);
    asm volatile("cp.async.commit_group;");

    uint32_t aOff = (uint32_t)((lane & 15) * AROWB + (lane >> 4) * 16);
    uint32_t bOff = (uint32_t)((((lane & 7) + ((lane >> 4) << 3)) * AROWB)
                               + (((lane >> 3) & 1) * 16));

    float m0 = -INFINITY, m1 = -INFINITY, l0 = 0.f, l1 = 0.f;
    float o[8][4];
    #pragma unroll
    for (int nt = 0; nt < 8; nt++)
        #pragma unroll
        for (int c = 0; c < 4; c++) o[nt][c] = 0.f;

    const float* ab = alibi + ((size_t)h * SEQ + i0 + wm + (lane >> 2)) * SEQ + 2 * (lane & 3);

    for (int jt = 0; jt < SEQ / 64; jt++) {
        int s = jt & 1;

        // Preload alibi into the S accumulator (issues LDGs early; latency
        // hidden behind the cp.async wait + barrier + QK MMAs).
        float sc[8][4];
        const float* abj = ab + jt * 64;
        #pragma unroll
        for (int nt = 0; nt < 8; nt++) {
            float2 al0 = *(const float2*)(abj + nt * 8);
            float2 al1 = *(const float2*)(abj + 8 * SEQ + nt * 8);
            sc[nt][0] = al0.x; sc[nt][1] = al0.y;
            sc[nt][2] = al1.x; sc[nt][3] = al1.y;
        }

        if (jt + 1 < SEQ / 64) {
            load_kv((jt + 1) * 64, s ^ 1);
            asm volatile("cp.async.commit_group;");
            asm volatile("cp.async.wait_group 1;" ::: "memory");
        } else {
            asm volatile("cp.async.wait_group 0;" ::: "memory");
        }
        __syncthreads();

        uint32_t ksm = sq + QSM_B + s * KVSTG;
        uint32_t vsm = ksm + KVTILE;

        // S = (Q*scale) K^T + alibi
        #pragma unroll
        for (int kt = 0; kt < 4; kt++) {
            uint32_t a[4];
            ldsm4(a, sq + wm * AROWB + kt * 32 + aOff);
            #pragma unroll
            for (int p = 0; p < 4; p++) {
                uint32_t b[4];
                ldsm4(b, ksm + p * 16 * AROWB + kt * 32 + bOff);
                mma16816(sc[2*p],     a, b[0], b[1]);
                mma16816(sc[2*p + 1], a, b[2], b[3]);
            }
        }

        // online softmax
        float mx0 = -INFINITY, mx1 = -INFINITY;
        #pragma unroll
        for (int nt = 0; nt < 8; nt++) {
            mx0 = fmaxf(mx0, fmaxf(sc[nt][0], sc[nt][1]));
            mx1 = fmaxf(mx1, fmaxf(sc[nt][2], sc[nt][3]));
        }
        mx0 = fmaxf(mx0, __shfl_xor_sync(0xffffffffu, mx0, 1));
        mx0 = fmaxf(mx0, __shfl_xor_sync(0xffffffffu, mx0, 2));
        mx1 = fmaxf(mx1, __shfl_xor_sync(0xffffffffu, mx1, 1));
        mx1 = fmaxf(mx1, __shfl_xor_sync(0xffffffffu, mx1, 2));

        float mn0 = fmaxf(m0, mx0), mn1 = fmaxf(m1, mx1);
        float alpha0 = __expf(m0 - mn0), alpha1 = __expf(m1 - mn1);
        m0 = mn0; m1 = mn1;

        float rs0 = 0.f, rs1 = 0.f;
        #pragma unroll
        for (int nt = 0; nt < 8; nt++) {
            sc[nt][0] = __expf(sc[nt][0] - mn0); rs0 += sc[nt][0];
            sc[nt][1] = __expf(sc[nt][1] - mn0); rs0 += sc[nt][1];
            sc[nt][2] = __expf(sc[nt][2] - mn1); rs1 += sc[nt][2];
            sc[nt][3] = __expf(sc[nt][3] - mn1); rs1 += sc[nt][3];
        }
        rs0 += __shfl_xor_sync(0xffffffffu, rs0, 1);
        rs0 += __shfl_xor_sync(0xffffffffu, rs0, 2);
        rs1 += __shfl_xor_sync(0xffffffffu, rs1, 1);
        rs1 += __shfl_xor_sync(0xffffffffu, rs1, 2);
        l0 = l0 * alpha0 + rs0;
        l1 = l1 * alpha1 + rs1;

        #pragma unroll
        for (int nt = 0; nt < 8; nt++) {
            o[nt][0] *= alpha0; o[nt][1] *= alpha0;
            o[nt][2] *= alpha1; o[nt][3] *= alpha1;
        }

        // O += P V
        #pragma unroll
        for (int kt = 0; kt < 4; kt++) {
            uint32_t pa[4];
            pa[0] = packh2(sc[2*kt][0],     sc[2*kt][1]);
            pa[1] = packh2(sc[2*kt][2],     sc[2*kt][3]);
            pa[2] = packh2(sc[2*kt + 1][0], sc[2*kt + 1][1]);
            pa[3] = packh2(sc[2*kt + 1][2], sc[2*kt + 1][3]);
            #pragma unroll
            for (int dp = 0; dp < 4; dp++) {
                uint32_t vbf[4];
                ldsm4t(vbf, vsm + kt * 16 * AROWB + dp * 32 + aOff);
                mma16816(o[2*dp],     pa, vbf[0], vbf[1]);
                mma16816(o[2*dp + 1], pa, vbf[2], vbf[3]);
            }
        }
        __syncthreads();
    }

    float invl0 = 1.0f / l0, invl1 = 1.0f / l1;
    size_t r0 = (size_t)bi * SEQ + i0 + wm + (lane >> 2);
    int colb = h * DHEAD + 2 * (lane & 3);
    #pragma unroll
    for (int nt = 0; nt < 8; nt++) {
        float y0 = o[nt][0] * invl0, y1 = o[nt][1] * invl0;
        float y2 = o[nt][2] * invl1, y3 = o[nt][3] * invl1;
        __half h0 = __float2half_rn(y0), h1 = __float2half_rn(y1);
        __half h2 = __float2half_rn(y2), h3 = __float2half_rn(y3);
        size_t p0 = r0 * DIMC + colb + nt * 8;
        size_t p1 = (r0 + 8) * DIMC + colb + nt * 8;
        *(__half2*)(ohi + p0) = __halves2half2(h0, h1);
        *(__half2*)(ohi + p1) = __halves2half2(h2, h3);
        *(__half2*)(olo + p0) = __halves2half2(
            __float2half_rn(y0 - __half2float(h0)), __float2half_rn(y1 - __half2float(h1)));
        *(__half2*)(olo + p1) = __halves2half2(
            __float2half_rn(y2 - __half2float(h2)), __float2half_rn(y3 - __half2float(h3)));
    }
}

// ---------------------------------------------------------------------------
extern "C" void kernel_launch(void* const* d_in, const int* in_sizes, int n_in,
                              void* d_out, int out_size) {
    const float* x     = (const float*)d_in[0];
    const float* ctx   = (const float*)d_in[1];
    const float* alibi = (const float*)d_in[2];
    const float* Wq    = (const float*)d_in[3];
    const float* Wk    = (const float*)d_in[4];
    const float* Wv    = (const float*)d_in[5];
    const float* Wo    = (const float*)d_in[6];
    const float* bo    = (const float*)d_in[7];
    const float* ln_w  = (const float*)d_in[8];
    const float* ln_b  = (const float*)d_in[9];
    float* out = (float*)d_out;

    __half *xhi, *chi, *ahi, *alo, *wb, *qh, *kh, *vh;
    cudaGetSymbolAddress((void**)&xhi, g_xhi);
    cudaGetSymbolAddress((void**)&chi, g_chi);
    cudaGetSymbolAddress((void**)&ahi, g_ahi);
    cudaGetSymbolAddress((void**)&alo, g_alo);
    cudaGetSymbolAddress((void**)&wb,  g_wb);
    cudaGetSymbolAddress((void**)&qh,  g_qh);
    cudaGetSymbolAddress((void**)&kh,  g_kh);
    cudaGetSymbolAddress((void**)&vh,  g_vh);

    size_t wsz = (size_t)DIMC * DIMC;
    __half *wq16 = wb;
    __half *wk16 = wb + wsz;
    __half *wv16 = wb + 2 * wsz;
    __half *wo16 = wb + 3 * wsz;

    dim3 gl(NROWS, 2);
    ln_kernel<<<gl, 256>>>(x, ctx, ln_w, ln_b, xhi, chi);

    int n4 = DIMC * DIMC / 4;
    dim3 gc(n4 / 256, 4);
    cvt_kernel<<<gc, 256>>>((const float4*)Wq, (const float4*)Wk,
                            (const float4*)Wv, (const float4*)Wo, wb, n4);

    cudaFuncSetAttribute(qkv_gemm, cudaFuncAttributeMaxDynamicSharedMemorySize, GSMEM1);
    cudaFuncSetAttribute(wo_gemm,  cudaFuncAttributeMaxDynamicSharedMemorySize, GSMEM2);

    dim3 gq(DIMC / 128, NROWS / 128, 3);
    qkv_gemm<<<gq, 256, GSMEM1>>>(xhi, chi, wq16, wk16, wv16, qh, kh, vh);

    cudaFuncSetAttribute(attn_kernel, cudaFuncAttributeMaxDynamicSharedMemorySize, ASMEM);
    dim3 ga(SEQ / 128, NB * NHEAD);
    attn_kernel<<<ga, 256, ASMEM>>>(qh, kh, vh, alibi, ahi, alo);

    dim3 gg(DIMC / 128, NROWS / 128);
    wo_gemm<<<gg, 256, GSMEM2>>>(ahi, alo, wo16, bo, out);
}